// round 6
// baseline (speedup 1.0000x reference)
#include <cuda_runtime.h>
#include <cstddef>
#include <cstdint>
#include <math.h>

#define SEQ   512
#define BATCH 256
#define INP   256
#define HID   512

typedef unsigned long long u64;

// ---------- packed f32x2 helpers (sm_103a) ----------
__device__ __forceinline__ u64 dup2(float x) {
    u64 r; asm("mov.b64 %0,{%1,%1};" : "=l"(r) : "f"(x)); return r;
}
__device__ __forceinline__ void fma2(u64& d, u64 a, u64 b) {
    asm("fma.rn.f32x2 %0,%1,%2,%0;" : "+l"(d) : "l"(a), "l"(b));
}
__device__ __forceinline__ void add2(u64& d, u64 a) {
    asm("add.rn.f32x2 %0,%0,%1;" : "+l"(d) : "l"(a));
}
__device__ __forceinline__ float2 upk(u64 v) {
    float2 f; asm("mov.b64 {%0,%1},%2;" : "=f"(f.x), "=f"(f.y) : "l"(v)); return f;
}

// ---------- sync helpers ----------
__device__ __forceinline__ unsigned ld_acq(const unsigned* p) {
    unsigned v;
    asm volatile("ld.acquire.gpu.global.b32 %0,[%1];" : "=r"(v) : "l"(p) : "memory");
    return v;
}
__device__ __forceinline__ void st_rel(unsigned* p, unsigned v) {
    asm volatile("st.release.gpu.global.b32 [%0],%1;" :: "l"(p), "r"(v) : "memory");
}

// ---------- fast activations ----------
__device__ __forceinline__ float sig_f(float z) {
    return __fdividef(1.0f, 1.0f + __expf(-z));
}
__device__ __forceinline__ float tanh_f(float z) {
    return 1.0f - __fdividef(2.0f, __expf(2.0f * z) + 1.0f);
}

// ---------- scratch ----------
__device__ float g_xp[(size_t)SEQ * BATCH * 3 * HID];
__device__ float g_h[2][BATCH * HID];
__device__ unsigned g_cnt[8 * 32];
__device__ unsigned g_gen[8 * 32];

// ============================================================================
// Projection GEMM (unchanged): XP = X @ U^T + b for 3 weight sets.
// ============================================================================
__global__ void __launch_bounds__(256) proj_kernel(
    const float* __restrict__ X,
    const float* __restrict__ Uc, const float* __restrict__ bc,
    const float* __restrict__ Ua, const float* __restrict__ ba,
    const float* __restrict__ Uh, const float* __restrict__ bh)
{
    __shared__ __align__(16) float As[16][128];
    __shared__ __align__(16) float Bs[16][128];

    const int nt = blockIdx.x;
    const int mt = blockIdx.y;
    const int n0 = nt * 128, m0 = mt * 128;
    const int region = n0 >> 9;
    const float* __restrict__ U    = (region == 0) ? Uc : (region == 1 ? Ua : Uh);
    const float* __restrict__ bias = (region == 0) ? bc : (region == 1 ? ba : bh);
    const int nl0 = n0 & 511;

    const int tid = threadIdx.x;
    const int tn = tid & 15;
    const int tm = tid >> 4;
    const int lr = tid & 127;
    const int lc = tid >> 7;

    u64 acc[8][4];
    #pragma unroll
    for (int i = 0; i < 8; i++)
        #pragma unroll
        for (int q = 0; q < 4; q++) acc[i][q] = 0ull;

    for (int kt = 0; kt < 16; kt++) {
        const int k0 = kt * 16;
        #pragma unroll
        for (int half = 0; half < 2; half++) {
            int c = lc + 2 * half;
            float4 v = *(const float4*)&X[(size_t)(m0 + lr) * INP + k0 + c * 4];
            As[c * 4 + 0][lr] = v.x; As[c * 4 + 1][lr] = v.y;
            As[c * 4 + 2][lr] = v.z; As[c * 4 + 3][lr] = v.w;
        }
        #pragma unroll
        for (int half = 0; half < 2; half++) {
            int c = lc + 2 * half;
            float4 v = *(const float4*)&U[(size_t)(nl0 + lr) * INP + k0 + c * 4];
            Bs[c * 4 + 0][lr] = v.x; Bs[c * 4 + 1][lr] = v.y;
            Bs[c * 4 + 2][lr] = v.z; Bs[c * 4 + 3][lr] = v.w;
        }
        __syncthreads();

        #pragma unroll
        for (int k = 0; k < 16; k++) {
            float4 a0 = *(const float4*)&As[k][tm * 8];
            float4 a1 = *(const float4*)&As[k][tm * 8 + 4];
            ulonglong2 b0 = *(const ulonglong2*)&Bs[k][tn * 8];
            ulonglong2 b1 = *(const ulonglong2*)&Bs[k][tn * 8 + 4];
            u64 ad[8];
            ad[0] = dup2(a0.x); ad[1] = dup2(a0.y); ad[2] = dup2(a0.z); ad[3] = dup2(a0.w);
            ad[4] = dup2(a1.x); ad[5] = dup2(a1.y); ad[6] = dup2(a1.z); ad[7] = dup2(a1.w);
            #pragma unroll
            for (int i = 0; i < 8; i++) {
                fma2(acc[i][0], ad[i], b0.x);
                fma2(acc[i][1], ad[i], b0.y);
                fma2(acc[i][2], ad[i], b1.x);
                fma2(acc[i][3], ad[i], b1.y);
            }
        }
        __syncthreads();
    }

    float bv[8];
    #pragma unroll
    for (int q = 0; q < 8; q++) bv[q] = bias[nl0 + tn * 8 + q];
    #pragma unroll
    for (int i = 0; i < 8; i++) {
        const size_t m = (size_t)m0 + tm * 8 + i;
        float2 p0 = upk(acc[i][0]), p1 = upk(acc[i][1]);
        float2 p2 = upk(acc[i][2]), p3 = upk(acc[i][3]);
        float4 o0 = make_float4(p0.x + bv[0], p0.y + bv[1], p1.x + bv[2], p1.y + bv[3]);
        float4 o1 = make_float4(p2.x + bv[4], p2.y + bv[5], p3.x + bv[6], p3.y + bv[7]);
        float* dst = &g_xp[m * 1536 + n0 + tn * 8];
        *(float4*)dst       = o0;
        *(float4*)(dst + 4) = o1;
    }
}

// ============================================================================
// Recurrence v6: R4 structure + per-warp slice staging (pair named barrier
// instead of CTA-wide sync) + xp prefetch hoisted before the inter-CTA
// counting barrier. 512 threads, warp = (kslice in 8) x (jhalf in 2).
// ============================================================================
#define HSTR 516

__global__ void __launch_bounds__(512, 1) recur_kernel(
    const float* __restrict__ h_in,
    const float* __restrict__ Wc, const float* __restrict__ Wa,
    float* __restrict__ out)
{
    extern __shared__ float sm[];
    float* Ws  = sm;                     // [512k][64]: [k][j]=Wc, [k][32+j]=Wa
    float* Hs  = sm + 32768;             // [32 b][HSTR]
    float* Red = sm + 32768 + 16512;     // partials
    ulonglong2* RedU = (ulonglong2*)Red;

    const int ct = blockIdx.x;           // 0..127
    const int jt = ct & 15, bt = ct >> 4;
    const int j0 = jt * 32, b0 = bt * 32;
    const int tid = threadIdx.x;
    const int w = tid >> 5, lane = tid & 31;
    const int ks = w >> 1, jh = w & 1;   // k-slice (8), j-half (2)
    const int jg = lane >> 3;
    const int bl = lane & 7;
    const int kw0 = ks * 64;
    const int jwl = jh * 16 + jg * 4;

    // consumer mapping: tid = b*16 + jp, j = jp*2 (+0,+1)
    const int cb  = tid >> 4;
    const int jp  = tid & 15;
    const int cjh = jp >> 3;
    const int cjg = (jp >> 1) & 3;
    const int cje = (jp & 1) * 2;
    const int ci  = cb >> 3, cbl = cb & 7;
    const int rbase = (((cjh * 8 + ci) * 32 + cbl * 4 + cjg) << 2) + cje;

    const int ksm = ks & 3;
    const int pbase = ((ksm * 2 + jh) * 8) * 32 + bl * 4 + jg;

    // staging: warp (ks,jh) fills columns [c0, c0+32) for all 32 rows
    const int c0 = ks * 64 + jh * 32;
    const int sr = lane >> 3;            // row-in-group 0..3
    const int sc = (lane & 7) << 2;      // col offset 0..28 (coalesced 128B/row)

    // ---- stage weights (one-time) ----
    for (int idx = tid; idx < 32 * 128; idx += 512) {
        int j = idx >> 7, k = (idx & 127) << 2;
        float4 wc = __ldcg((const float4*)&Wc[(size_t)(j0 + j) * HID + k]);
        float4 wa = __ldcg((const float4*)&Wa[(size_t)(j0 + j) * HID + k]);
        Ws[(k + 0) * 64 + j] = wc.x; Ws[(k + 1) * 64 + j] = wc.y;
        Ws[(k + 2) * 64 + j] = wc.z; Ws[(k + 3) * 64 + j] = wc.w;
        Ws[(k + 0) * 64 + 32 + j] = wa.x; Ws[(k + 1) * 64 + 32 + j] = wa.y;
        Ws[(k + 2) * 64 + 32 + j] = wa.z; Ws[(k + 3) * 64 + 32 + j] = wa.w;
    }

    unsigned* cnt = &g_cnt[bt * 32];
    unsigned* gen = &g_gen[bt * 32];
    __shared__ unsigned s_g0;
    if (tid == 0) s_g0 = *gen;           // replay-safe generation base
    __syncthreads();
    const unsigned g0 = s_g0;

    // initial xp prefetch (t = 0)
    float2 xc, xa, xh;
    {
        const size_t crow = (size_t)0 * BATCH + b0 + cb;
        const float* xpb = &g_xp[crow * 1536 + j0 + jp * 2];
        xc = __ldcg((const float2*)(xpb));
        xa = __ldcg((const float2*)(xpb + 512));
        xh = __ldcg((const float2*)(xpb + 1024));
    }

    for (int t = 0; t < SEQ; t++) {
        // ---- per-warp: stage my 32 h-columns (coalesced), pair-sync ----
        const float* __restrict__ hsrc = (t == 0) ? h_in : g_h[t & 1];
        #pragma unroll
        for (int it = 0; it < 8; it++) {
            int r = it * 4 + sr;
            float4 v = __ldcg((const float4*)&hsrc[(size_t)(b0 + r) * HID + c0 + sc]);
            *(float4*)&Hs[r * HSTR + c0 + sc] = v;
        }
        asm volatile("bar.sync %0, 64;" :: "r"(1 + ks) : "memory");

        // ---- matvec over this warp's 64-k slice, 16j x 32b ----
        u64 acc[2][4][2];
        #pragma unroll
        for (int m = 0; m < 2; m++)
            #pragma unroll
            for (int i = 0; i < 4; i++) { acc[m][i][0] = 0ull; acc[m][i][1] = 0ull; }

        #pragma unroll 2
        for (int k4 = 0; k4 < 16; k4++) {
            const int kk = kw0 + k4 * 4;
            float4 hv[4];
            #pragma unroll
            for (int i = 0; i < 4; i++)
                hv[i] = *(const float4*)&Hs[(bl + 8 * i) * HSTR + kk];
            #pragma unroll
            for (int q = 0; q < 4; q++) {
                const float* wr = &Ws[(kk + q) * 64 + jwl];
                ulonglong2 wc = *(const ulonglong2*)wr;
                ulonglong2 wa = *(const ulonglong2*)(wr + 32);
                #pragma unroll
                for (int i = 0; i < 4; i++) {
                    float hq = (q == 0) ? hv[i].x : (q == 1) ? hv[i].y
                             : (q == 2) ? hv[i].z : hv[i].w;
                    u64 hd = dup2(hq);
                    fma2(acc[0][i][0], hd, wc.x); fma2(acc[0][i][1], hd, wc.y);
                    fma2(acc[1][i][0], hd, wa.x); fma2(acc[1][i][1], hd, wa.y);
                }
            }
        }

        // ---- round 1: k-slices 0-3 store partials ----
        if (ks < 4) {
            #pragma unroll
            for (int m = 0; m < 2; m++)
                #pragma unroll
                for (int i = 0; i < 4; i++)
                    RedU[pbase + (m * 4 + i) * 32] =
                        make_ulonglong2(acc[m][i][0], acc[m][i][1]);
        }
        __syncthreads();
        // ---- round 2: k-slices 4-7 accumulate in place ----
        if (ks >= 4) {
            #pragma unroll
            for (int m = 0; m < 2; m++)
                #pragma unroll
                for (int i = 0; i < 4; i++) {
                    const int idx = pbase + (m * 4 + i) * 32;
                    ulonglong2 v = RedU[idx];
                    add2(acc[m][i][0], v.x); add2(acc[m][i][1], v.y);
                    RedU[idx] = make_ulonglong2(acc[m][i][0], acc[m][i][1]);
                }
        }
        __syncthreads();

        // ---- consumer: sum 4 regions, fused gated epilogue, stores ----
        {
            float2 hc = make_float2(0.f, 0.f), ha = make_float2(0.f, 0.f);
            #pragma unroll
            for (int r = 0; r < 4; r++) {
                float2 vc = *(const float2*)&Red[rbase + r * 2048];
                float2 va = *(const float2*)&Red[rbase + r * 2048 + 512];
                hc.x += vc.x; hc.y += vc.y;
                ha.x += va.x; ha.y += va.y;
            }
            float2 hp = *(const float2*)&Hs[cb * HSTR + j0 + jp * 2];
            const size_t crow = (size_t)t * BATCH + b0 + cb;

            float r0, r1;
            {
                float cg = sig_f(xc.x + hc.x);
                float ag = 1.0f + tanh_f(xa.x + ha.x);
                r0 = cg * hp.x + (1.0f - cg) * tanh_f(xh.x + ag * hp.x);
            }
            {
                float cg = sig_f(xc.y + hc.y);
                float ag = 1.0f + tanh_f(xa.y + ha.y);
                r1 = cg * hp.y + (1.0f - cg) * tanh_f(xh.y + ag * hp.y);
            }
            float2 rv = make_float2(r0, r1);
            __stcg((float2*)&out[crow * HID + j0 + jp * 2], rv);
            __stcg((float2*)&g_h[(t + 1) & 1][(size_t)(b0 + cb) * HID + j0 + jp * 2], rv);
            if (t == SEQ - 1)
                __stcg((float2*)&out[(size_t)SEQ * BATCH * HID +
                                     (size_t)(b0 + cb) * HID + j0 + jp * 2], rv);
        }

        // ---- prefetch next step's xp (overlaps the barrier wait) ----
        if (t < SEQ - 1) {
            const size_t nrow = (size_t)(t + 1) * BATCH + b0 + cb;
            const float* nxpb = &g_xp[nrow * 1536 + j0 + jp * 2];
            xc = __ldcg((const float2*)(nxpb));
            xa = __ldcg((const float2*)(nxpb + 512));
            xh = __ldcg((const float2*)(nxpb + 1024));

            // ---- lean 16-way inter-CTA barrier (per batch tile) ----
            __syncthreads();
            if (tid == 0) {
                __threadfence();
                const unsigned target = g0 + (unsigned)t + 1u;
                if (atomicAdd(cnt, 1u) == 15u) {
                    atomicExch(cnt, 0u);
                    __threadfence();
                    st_rel(gen, target);
                } else {
                    while (ld_acq(gen) != target) { }
                }
            }
            __syncthreads();
        }
    }
}

// ============================================================================
extern "C" void kernel_launch(void* const* d_in, const int* in_sizes, int n_in,
                              void* d_out, int out_size)
{
    const float* X  = (const float*)d_in[0];
    const float* h0 = (const float*)d_in[1];
    const float* Uc = (const float*)d_in[2];
    const float* Wc = (const float*)d_in[3];
    const float* bc = (const float*)d_in[4];
    const float* Ua = (const float*)d_in[5];
    const float* Wa = (const float*)d_in[6];
    const float* ba = (const float*)d_in[7];
    const float* Uh = (const float*)d_in[8];
    const float* bh = (const float*)d_in[9];
    float* out = (float*)d_out;

    const size_t shmem = (size_t)(32768 + 16512 + 8192) * sizeof(float); // 229888 B
    cudaFuncSetAttribute(recur_kernel, cudaFuncAttributeMaxDynamicSharedMemorySize,
                         (int)shmem);

    dim3 pg(12, 1024);
    proj_kernel<<<pg, 256>>>(X, Uc, bc, Ua, ba, Uh, bh);
    recur_kernel<<<128, 512, shmem>>>(h0, Wc, Wa, out);
}

// round 9
// speedup vs baseline: 1.5947x; 1.5947x over previous
#include <cuda_runtime.h>
#include <cstddef>
#include <cstdint>
#include <math.h>

#define SEQ   512
#define BATCH 256
#define INP   256
#define HID   512

typedef unsigned long long u64;

// ---------- packed f32x2 helpers (sm_103a) ----------
__device__ __forceinline__ u64 dup2(float x) {
    u64 r; asm("mov.b64 %0,{%1,%1};" : "=l"(r) : "f"(x)); return r;
}
__device__ __forceinline__ void fma2(u64& d, u64 a, u64 b) {
    asm("fma.rn.f32x2 %0,%1,%2,%0;" : "+l"(d) : "l"(a), "l"(b));
}
__device__ __forceinline__ void add2(u64& d, u64 a) {
    asm("add.rn.f32x2 %0,%0,%1;" : "+l"(d) : "l"(a));
}
__device__ __forceinline__ float2 upk(u64 v) {
    float2 f; asm("mov.b64 {%0,%1},%2;" : "=f"(f.x), "=f"(f.y) : "l"(v)); return f;
}

// ---------- sync helpers ----------
__device__ __forceinline__ unsigned ld_acq(const unsigned* p) {
    unsigned v;
    asm volatile("ld.acquire.gpu.global.b32 %0,[%1];" : "=r"(v) : "l"(p) : "memory");
    return v;
}
__device__ __forceinline__ void st_rel(unsigned* p, unsigned v) {
    asm volatile("st.release.gpu.global.b32 [%0],%1;" :: "l"(p), "r"(v) : "memory");
}

// ---------- fast activations ----------
__device__ __forceinline__ float sig_f(float z) {
    return __fdividef(1.0f, 1.0f + __expf(-z));
}
__device__ __forceinline__ float tanh_f(float z) {
    return 1.0f - __fdividef(2.0f, __expf(2.0f * z) + 1.0f);
}

// ---------- scratch ----------
__device__ float g_xp[(size_t)SEQ * BATCH * 3 * HID];
__device__ float g_h[2][BATCH * HID];
__device__ unsigned g_cnt[8 * 32];
__device__ unsigned g_gen[8 * 32];

// ============================================================================
// Projection GEMM (unchanged): XP = X @ U^T + b for 3 weight sets.
// ============================================================================
__global__ void __launch_bounds__(256) proj_kernel(
    const float* __restrict__ X,
    const float* __restrict__ Uc, const float* __restrict__ bc,
    const float* __restrict__ Ua, const float* __restrict__ ba,
    const float* __restrict__ Uh, const float* __restrict__ bh)
{
    __shared__ __align__(16) float As[16][128];
    __shared__ __align__(16) float Bs[16][128];

    const int nt = blockIdx.x;
    const int mt = blockIdx.y;
    const int n0 = nt * 128, m0 = mt * 128;
    const int region = n0 >> 9;
    const float* __restrict__ U    = (region == 0) ? Uc : (region == 1 ? Ua : Uh);
    const float* __restrict__ bias = (region == 0) ? bc : (region == 1 ? ba : bh);
    const int nl0 = n0 & 511;

    const int tid = threadIdx.x;
    const int tn = tid & 15;
    const int tm = tid >> 4;
    const int lr = tid & 127;
    const int lc = tid >> 7;

    u64 acc[8][4];
    #pragma unroll
    for (int i = 0; i < 8; i++)
        #pragma unroll
        for (int q = 0; q < 4; q++) acc[i][q] = 0ull;

    for (int kt = 0; kt < 16; kt++) {
        const int k0 = kt * 16;
        #pragma unroll
        for (int half = 0; half < 2; half++) {
            int c = lc + 2 * half;
            float4 v = *(const float4*)&X[(size_t)(m0 + lr) * INP + k0 + c * 4];
            As[c * 4 + 0][lr] = v.x; As[c * 4 + 1][lr] = v.y;
            As[c * 4 + 2][lr] = v.z; As[c * 4 + 3][lr] = v.w;
        }
        #pragma unroll
        for (int half = 0; half < 2; half++) {
            int c = lc + 2 * half;
            float4 v = *(const float4*)&U[(size_t)(nl0 + lr) * INP + k0 + c * 4];
            Bs[c * 4 + 0][lr] = v.x; Bs[c * 4 + 1][lr] = v.y;
            Bs[c * 4 + 2][lr] = v.z; Bs[c * 4 + 3][lr] = v.w;
        }
        __syncthreads();

        #pragma unroll
        for (int k = 0; k < 16; k++) {
            float4 a0 = *(const float4*)&As[k][tm * 8];
            float4 a1 = *(const float4*)&As[k][tm * 8 + 4];
            ulonglong2 b0 = *(const ulonglong2*)&Bs[k][tn * 8];
            ulonglong2 b1 = *(const ulonglong2*)&Bs[k][tn * 8 + 4];
            u64 ad[8];
            ad[0] = dup2(a0.x); ad[1] = dup2(a0.y); ad[2] = dup2(a0.z); ad[3] = dup2(a0.w);
            ad[4] = dup2(a1.x); ad[5] = dup2(a1.y); ad[6] = dup2(a1.z); ad[7] = dup2(a1.w);
            #pragma unroll
            for (int i = 0; i < 8; i++) {
                fma2(acc[i][0], ad[i], b0.x);
                fma2(acc[i][1], ad[i], b0.y);
                fma2(acc[i][2], ad[i], b1.x);
                fma2(acc[i][3], ad[i], b1.y);
            }
        }
        __syncthreads();
    }

    float bv[8];
    #pragma unroll
    for (int q = 0; q < 8; q++) bv[q] = bias[nl0 + tn * 8 + q];
    #pragma unroll
    for (int i = 0; i < 8; i++) {
        const size_t m = (size_t)m0 + tm * 8 + i;
        float2 p0 = upk(acc[i][0]), p1 = upk(acc[i][1]);
        float2 p2 = upk(acc[i][2]), p3 = upk(acc[i][3]);
        float4 o0 = make_float4(p0.x + bv[0], p0.y + bv[1], p1.x + bv[2], p1.y + bv[3]);
        float4 o1 = make_float4(p2.x + bv[4], p2.y + bv[5], p3.x + bv[6], p3.y + bv[7]);
        float* dst = &g_xp[m * 1536 + n0 + tn * 8];
        *(float4*)dst       = o0;
        *(float4*)(dst + 4) = o1;
    }
}

// ============================================================================
// Recurrence v8 = EXACT R4 skeleton (verified 8119us) + ONE delta:
// the consumer xp loads for step t+1 are issued before the inter-CTA barrier
// of step t (register prefetch), hiding their latency behind the barrier wait,
// h staging and matvec. No other changes.
// ============================================================================
#define HSTR 516

__global__ void __launch_bounds__(512, 1) recur_kernel(
    const float* __restrict__ h_in,
    const float* __restrict__ Wc, const float* __restrict__ Wa,
    float* __restrict__ out)
{
    extern __shared__ float sm[];
    float* Ws  = sm;                     // [512k][64]: [k][j]=Wc, [k][32+j]=Wa
    float* Hs  = sm + 32768;             // [32 b][HSTR]
    float* Red = sm + 32768 + 16512;     // partials, 2048 x 16B chunks
    ulonglong2* RedU = (ulonglong2*)Red;

    const int ct = blockIdx.x;           // 0..127
    const int jt = ct & 15, bt = ct >> 4;
    const int j0 = jt * 32, b0 = bt * 32;
    const int tid = threadIdx.x;
    const int w = tid >> 5, lane = tid & 31;
    const int ks = w >> 1, jh = w & 1;   // k-slice (8), j-half (2)
    const int jg = lane >> 3;
    const int bl = lane & 7;
    const int kw0 = ks * 64;
    const int jwl = jh * 16 + jg * 4;

    // consumer mapping: tid = b*16 + jp, j = jp*2 (+0,+1)
    const int cb  = tid >> 4;
    const int jp  = tid & 15;
    const int cjh = jp >> 3;
    const int cjg = (jp >> 1) & 3;
    const int cje = (jp & 1) * 2;
    const int ci  = cb >> 3, cbl = cb & 7;
    const int rbase = (((cjh * 8 + ci) * 32 + cbl * 4 + cjg) << 2) + cje;

    const int ksm = ks & 3;
    const int pbase = ((ksm * 2 + jh) * 8) * 32 + bl * 4 + jg;

    // ---- stage weights (one-time) ----
    for (int idx = tid; idx < 32 * 128; idx += 512) {
        int j = idx >> 7, k = (idx & 127) << 2;
        float4 wc = __ldcg((const float4*)&Wc[(size_t)(j0 + j) * HID + k]);
        float4 wa = __ldcg((const float4*)&Wa[(size_t)(j0 + j) * HID + k]);
        Ws[(k + 0) * 64 + j] = wc.x; Ws[(k + 1) * 64 + j] = wc.y;
        Ws[(k + 2) * 64 + j] = wc.z; Ws[(k + 3) * 64 + j] = wc.w;
        Ws[(k + 0) * 64 + 32 + j] = wa.x; Ws[(k + 1) * 64 + 32 + j] = wa.y;
        Ws[(k + 2) * 64 + 32 + j] = wa.z; Ws[(k + 3) * 64 + 32 + j] = wa.w;
    }

    unsigned* cnt = &g_cnt[bt * 32];
    unsigned* gen = &g_gen[bt * 32];
    __shared__ unsigned s_g0;
    if (tid == 0) s_g0 = *gen;           // replay-safe generation base
    __syncthreads();
    const unsigned g0 = s_g0;

    // ---- xp prefetch for t = 0 (consumer-mapped) ----
    float2 xc, xa, xh;
    {
        const size_t crow0 = (size_t)0 * BATCH + b0 + cb;
        const float* xpb = &g_xp[crow0 * 1536 + j0 + jp * 2];
        xc = __ldcg((const float2*)(xpb));
        xa = __ldcg((const float2*)(xpb + 512));
        xh = __ldcg((const float2*)(xpb + 1024));
    }

    for (int t = 0; t < SEQ; t++) {
        // stage h tile (CTA-wide, identical to R4)
        const float* __restrict__ hsrc = (t == 0) ? h_in : g_h[t & 1];
        for (int i = tid; i < 32 * 128; i += 512) {
            int r = i >> 7, c = (i & 127) << 2;
            *(float4*)&Hs[r * HSTR + c] =
                __ldcg((const float4*)&hsrc[(size_t)(b0 + r) * HID + c]);
        }
        __syncthreads();

        // ---- matvec over this warp's 64-k slice, 16j x 32b ----
        u64 acc[2][4][2];
        #pragma unroll
        for (int m = 0; m < 2; m++)
            #pragma unroll
            for (int i = 0; i < 4; i++) { acc[m][i][0] = 0ull; acc[m][i][1] = 0ull; }

        #pragma unroll 2
        for (int k4 = 0; k4 < 16; k4++) {
            const int kk = kw0 + k4 * 4;
            float4 hv[4];
            #pragma unroll
            for (int i = 0; i < 4; i++)
                hv[i] = *(const float4*)&Hs[(bl + 8 * i) * HSTR + kk];
            #pragma unroll
            for (int q = 0; q < 4; q++) {
                const float* wr = &Ws[(kk + q) * 64 + jwl];
                ulonglong2 wc = *(const ulonglong2*)wr;
                ulonglong2 wa = *(const ulonglong2*)(wr + 32);
                #pragma unroll
                for (int i = 0; i < 4; i++) {
                    float hq = (q == 0) ? hv[i].x : (q == 1) ? hv[i].y
                             : (q == 2) ? hv[i].z : hv[i].w;
                    u64 hd = dup2(hq);
                    fma2(acc[0][i][0], hd, wc.x); fma2(acc[0][i][1], hd, wc.y);
                    fma2(acc[1][i][0], hd, wa.x); fma2(acc[1][i][1], hd, wa.y);
                }
            }
        }

        // ---- round 1: k-slices 0-3 store partials ----
        if (ks < 4) {
            #pragma unroll
            for (int m = 0; m < 2; m++)
                #pragma unroll
                for (int i = 0; i < 4; i++)
                    RedU[pbase + (m * 4 + i) * 32] =
                        make_ulonglong2(acc[m][i][0], acc[m][i][1]);
        }
        __syncthreads();
        // ---- round 2: k-slices 4-7 accumulate in place ----
        if (ks >= 4) {
            #pragma unroll
            for (int m = 0; m < 2; m++)
                #pragma unroll
                for (int i = 0; i < 4; i++) {
                    const int idx = pbase + (m * 4 + i) * 32;
                    ulonglong2 v = RedU[idx];
                    add2(acc[m][i][0], v.x); add2(acc[m][i][1], v.y);
                    RedU[idx] = make_ulonglong2(acc[m][i][0], acc[m][i][1]);
                }
        }
        __syncthreads();

        // ---- consumer: sum 4 regions, fused gated epilogue, stores ----
        {
            float2 hc = make_float2(0.f, 0.f), ha = make_float2(0.f, 0.f);
            #pragma unroll
            for (int r = 0; r < 4; r++) {
                float2 vc = *(const float2*)&Red[rbase + r * 2048];
                float2 va = *(const float2*)&Red[rbase + r * 2048 + 512];
                hc.x += vc.x; hc.y += vc.y;
                ha.x += va.x; ha.y += va.y;
            }
            float2 hp = *(const float2*)&Hs[cb * HSTR + j0 + jp * 2];
            const size_t crow = (size_t)t * BATCH + b0 + cb;

            float r0, r1;
            {
                float cg = sig_f(xc.x + hc.x);
                float ag = 1.0f + tanh_f(xa.x + ha.x);
                r0 = cg * hp.x + (1.0f - cg) * tanh_f(xh.x + ag * hp.x);
            }
            {
                float cg = sig_f(xc.y + hc.y);
                float ag = 1.0f + tanh_f(xa.y + ha.y);
                r1 = cg * hp.y + (1.0f - cg) * tanh_f(xh.y + ag * hp.y);
            }
            float2 rv = make_float2(r0, r1);
            *(float2*)&out[crow * HID + j0 + jp * 2] = rv;
            *(float2*)&g_h[(t + 1) & 1][(size_t)(b0 + cb) * HID + j0 + jp * 2] = rv;
            if (t == SEQ - 1)
                *(float2*)&out[(size_t)SEQ * BATCH * HID +
                               (size_t)(b0 + cb) * HID + j0 + jp * 2] = rv;
        }

        // ---- THE DELTA: prefetch next step's xp before the barrier ----
        if (t < SEQ - 1) {
            const size_t nrow = (size_t)(t + 1) * BATCH + b0 + cb;
            const float* nxpb = &g_xp[nrow * 1536 + j0 + jp * 2];
            xc = __ldcg((const float2*)(nxpb));
            xa = __ldcg((const float2*)(nxpb + 512));
            xh = __ldcg((const float2*)(nxpb + 1024));

            // ---- lean 16-way inter-CTA barrier (identical to R4) ----
            __syncthreads();
            if (tid == 0) {
                __threadfence();
                const unsigned target = g0 + (unsigned)t + 1u;
                if (atomicAdd(cnt, 1u) == 15u) {
                    atomicExch(cnt, 0u);
                    __threadfence();
                    st_rel(gen, target);
                } else {
                    while (ld_acq(gen) != target) { }
                }
            }
            __syncthreads();
        }
    }
}

// ============================================================================
extern "C" void kernel_launch(void* const* d_in, const int* in_sizes, int n_in,
                              void* d_out, int out_size)
{
    const float* X  = (const float*)d_in[0];
    const float* h0 = (const float*)d_in[1];
    const float* Uc = (const float*)d_in[2];
    const float* Wc = (const float*)d_in[3];
    const float* bc = (const float*)d_in[4];
    const float* Ua = (const float*)d_in[5];
    const float* Wa = (const float*)d_in[6];
    const float* ba = (const float*)d_in[7];
    const float* Uh = (const float*)d_in[8];
    const float* bh = (const float*)d_in[9];
    float* out = (float*)d_out;

    const size_t shmem = (size_t)(32768 + 16512 + 8192) * sizeof(float); // 229888 B
    cudaFuncSetAttribute(recur_kernel, cudaFuncAttributeMaxDynamicSharedMemorySize,
                         (int)shmem);

    dim3 pg(12, 1024);
    proj_kernel<<<pg, 256>>>(X, Uc, bc, Ua, ba, Uh, bh);
    recur_kernel<<<128, 512, shmem>>>(h0, Wc, Wa, out);
}

// round 11
// speedup vs baseline: 1.8747x; 1.1756x over previous
#include <cuda_runtime.h>
#include <cuda_bf16.h>
#include <cstddef>
#include <cstdint>
#include <math.h>

#define SEQ   512
#define BATCH 256
#define INP   256
#define HID   512

typedef unsigned long long u64;

// ---------- packed f32x2 helpers (sm_103a) ----------
__device__ __forceinline__ u64 dup2(float x) {
    u64 r; asm("mov.b64 %0,{%1,%1};" : "=l"(r) : "f"(x)); return r;
}
__device__ __forceinline__ void fma2(u64& d, u64 a, u64 b) {
    asm("fma.rn.f32x2 %0,%1,%2,%0;" : "+l"(d) : "l"(a), "l"(b));
}
__device__ __forceinline__ void add2(u64& d, u64 a) {
    asm("add.rn.f32x2 %0,%0,%1;" : "+l"(d) : "l"(a));
}
__device__ __forceinline__ float2 upk(u64 v) {
    float2 f; asm("mov.b64 {%0,%1},%2;" : "=f"(f.x), "=f"(f.y) : "l"(v)); return f;
}

// ---------- sync helpers ----------
__device__ __forceinline__ unsigned ld_acq(const unsigned* p) {
    unsigned v;
    asm volatile("ld.acquire.gpu.global.b32 %0,[%1];" : "=r"(v) : "l"(p) : "memory");
    return v;
}
__device__ __forceinline__ void st_rel(unsigned* p, unsigned v) {
    asm volatile("st.release.gpu.global.b32 [%0],%1;" :: "l"(p), "r"(v) : "memory");
}

// ---------- fast activations ----------
__device__ __forceinline__ float sig_f(float z) {
    return __fdividef(1.0f, 1.0f + __expf(-z));
}
__device__ __forceinline__ float tanh_f(float z) {
    return 1.0f - __fdividef(2.0f, __expf(2.0f * z) + 1.0f);
}

// ---------- scratch ----------
__device__ float g_xp[(size_t)SEQ * BATCH * 3 * HID];
__device__ float g_h[2][BATCH * HID];
__device__ unsigned g_cnt[8 * 32];
__device__ unsigned g_gen[8 * 32];
// split-bf16 operands
__device__ __nv_bfloat16 g_xh[(size_t)SEQ * BATCH * INP];
__device__ __nv_bfloat16 g_xl[(size_t)SEQ * BATCH * INP];
__device__ __nv_bfloat16 g_uh[3 * HID * INP];
__device__ __nv_bfloat16 g_ul[3 * HID * INP];

// ---------- split helpers ----------
__device__ __forceinline__ uint32_t pck(__nv_bfloat16 a, __nv_bfloat16 b) {
    return (uint32_t)__bfloat16_as_ushort(a) | ((uint32_t)__bfloat16_as_ushort(b) << 16);
}
__device__ __forceinline__ void split4(float4 v, uint2& hi, uint2& lo) {
    __nv_bfloat16 h0 = __float2bfloat16_rn(v.x), h1 = __float2bfloat16_rn(v.y);
    __nv_bfloat16 h2 = __float2bfloat16_rn(v.z), h3 = __float2bfloat16_rn(v.w);
    __nv_bfloat16 l0 = __float2bfloat16_rn(v.x - __bfloat162float(h0));
    __nv_bfloat16 l1 = __float2bfloat16_rn(v.y - __bfloat162float(h1));
    __nv_bfloat16 l2 = __float2bfloat16_rn(v.z - __bfloat162float(h2));
    __nv_bfloat16 l3 = __float2bfloat16_rn(v.w - __bfloat162float(h3));
    hi = make_uint2(pck(h0, h1), pck(h2, h3));
    lo = make_uint2(pck(l0, l1), pck(l2, l3));
}

__global__ void __launch_bounds__(256) xsplit_kernel(const float* __restrict__ X) {
    const size_t total = (size_t)SEQ * BATCH * INP / 4;
    for (size_t f4 = (size_t)blockIdx.x * 256 + threadIdx.x; f4 < total;
         f4 += (size_t)gridDim.x * 256) {
        float4 v = __ldcg((const float4*)X + f4);
        uint2 hi, lo; split4(v, hi, lo);
        ((uint2*)g_xh)[f4] = hi;
        ((uint2*)g_xl)[f4] = lo;
    }
}

__global__ void __launch_bounds__(256) usplit_kernel(
    const float* __restrict__ Uc, const float* __restrict__ Ua,
    const float* __restrict__ Uh)
{
    const int mat = blockIdx.x >> 7;              // grid 384: 128 CTAs per matrix
    const int f4 = (blockIdx.x & 127) * 256 + threadIdx.x;   // 0..32767
    const float* src = (mat == 0) ? Uc : (mat == 1 ? Ua : Uh);
    float4 v = __ldcg((const float4*)src + f4);
    uint2 hi, lo; split4(v, hi, lo);
    ((uint2*)g_uh)[mat * 32768 + f4] = hi;
    ((uint2*)g_ul)[mat * 32768 + f4] = lo;
}

// ---------- mma / ldmatrix (base PTX, no 'a' features) ----------
__device__ __forceinline__ uint32_t smem_u32(const void* p) {
    uint32_t a;
    asm("{ .reg .u64 t; cvta.to.shared.u64 t,%1; cvt.u32.u64 %0,t; }" : "=r"(a) : "l"(p));
    return a;
}
__device__ __forceinline__ void ldsm4(uint32_t& r0, uint32_t& r1, uint32_t& r2,
                                      uint32_t& r3, uint32_t a) {
    asm volatile("ldmatrix.sync.aligned.m8n8.x4.shared.b16 {%0,%1,%2,%3},[%4];"
                 : "=r"(r0), "=r"(r1), "=r"(r2), "=r"(r3) : "r"(a));
}
__device__ __forceinline__ void ldsm2(uint32_t& r0, uint32_t& r1, uint32_t a) {
    asm volatile("ldmatrix.sync.aligned.m8n8.x2.shared.b16 {%0,%1},[%2];"
                 : "=r"(r0), "=r"(r1) : "r"(a));
}
__device__ __forceinline__ void mma16816(float* d, const uint32_t* a, const uint32_t* b) {
    asm volatile(
        "mma.sync.aligned.m16n8k16.row.col.f32.bf16.bf16.f32 "
        "{%0,%1,%2,%3},{%4,%5,%6,%7},{%8,%9},{%0,%1,%2,%3};"
        : "+f"(d[0]), "+f"(d[1]), "+f"(d[2]), "+f"(d[3])
        : "r"(a[0]), "r"(a[1]), "r"(a[2]), "r"(a[3]), "r"(b[0]), "r"(b[1]));
}

// SMEM layout for proj (bytes); rows padded to 528B (conflict-free ldmatrix)
#define PSTR 528
#define SM_PBIAS 0
#define SM_BH 1024
#define SM_BL (SM_BH + 64 * PSTR)        // 34816
#define SM_AH (SM_BL + 64 * PSTR)        // 68608
#define SM_AL (SM_AH + 128 * PSTR)       // 136192
#define SM_PROJ_TOT (SM_AL + 128 * PSTR) // 203776

// ============================================================================
// Tensor-core projection via mma.sync (HMMA bf16, split hi/lo, 3 products).
// grid = (24 n-slices of 64, 128 m-groups); each CTA does 8 m-tiles of 128.
// Warp grid 4m x 2n: warp tile 32m x 32n = 2 mtiles x 4 ntiles.
// ============================================================================
__global__ void __launch_bounds__(256, 1) proj_mma_kernel(
    const float* __restrict__ bc, const float* __restrict__ ba,
    const float* __restrict__ bh)
{
    extern __shared__ __align__(1024) char smem[];
    const uint32_t sb = smem_u32(smem);
    const int tid = threadIdx.x;
    const int wid = tid >> 5;
    const int lane = tid & 31;

    const int n0 = blockIdx.x * 64;
    const int region = n0 >> 9;
    const int nl0 = n0 & 511;
    const float* __restrict__ bias = (region == 0) ? bc : (region == 1 ? ba : bh);
    float* biasS = (float*)(smem + SM_PBIAS);
    if (tid < 64) biasS[tid] = bias[nl0 + tid];

    // ---- stage B (64n x 256k, hi+lo) one-time ----
    const __nv_bfloat16* ubase_h = g_uh + (size_t)region * HID * INP;
    const __nv_bfloat16* ubase_l = g_ul + (size_t)region * HID * INP;
    for (int idx = tid; idx < 4096; idx += 256) {     // 2 x 64 rows x 32 uint4
        int sel = idx >> 11;                          // 0=hi 1=lo
        int r = (idx >> 5) & 63, c = idx & 31;
        const __nv_bfloat16* src = (sel ? ubase_l : ubase_h) + (size_t)(nl0 + r) * INP;
        uint4 v = ((const uint4*)src)[c];
        *(uint4*)(smem + (sel ? SM_BL : SM_BH) + r * PSTR + c * 16) = v;
    }

    // per-thread ldmatrix address bases
    const int wm = wid & 3, wn = wid >> 2;
    const int msel = lane >> 3;
    const int arow = (msel & 1) * 8 + (lane & 7);
    const int acol16 = (msel >> 1);                   // 0/1 -> +16B
    uint32_t a_base[2];
    #pragma unroll
    for (int mt = 0; mt < 2; mt++)
        a_base[mt] = sb + SM_AH + (wm * 32 + mt * 16 + arow) * PSTR + acol16 * 16;
    uint32_t b_base[4];
    #pragma unroll
    for (int nt = 0; nt < 4; nt++)
        b_base[nt] = sb + SM_BH + (wn * 32 + nt * 8 + (lane & 7)) * PSTR
                   + ((lane >> 3) & 1) * 16;
    const uint32_t ADL = SM_AL - SM_AH;               // hi->lo deltas
    const uint32_t BDL = SM_BL - SM_BH;

    // ---- per m-tile loop ----
    for (int i = 0; i < 8; i++) {
        const int m0 = (blockIdx.y * 8 + i) * 128;
        __syncthreads();                               // A safe to overwrite

        // stage A (128m x 256k, hi+lo)
        for (int idx = tid; idx < 8192; idx += 256) {  // 2 x 128 rows x 32 uint4
            int sel = idx >> 12;
            int r = (idx >> 5) & 127, c = idx & 31;
            const __nv_bfloat16* src = (sel ? g_xl : g_xh) + (size_t)(m0 + r) * INP;
            uint4 v = __ldcg((const uint4*)src + c);
            *(uint4*)(smem + (sel ? SM_AL : SM_AH) + r * PSTR + c * 16) = v;
        }
        __syncthreads();

        float acc[2][4][4];
        #pragma unroll
        for (int mt = 0; mt < 2; mt++)
            #pragma unroll
            for (int nt = 0; nt < 4; nt++)
                #pragma unroll
                for (int q = 0; q < 4; q++) acc[mt][nt][q] = 0.0f;

        #pragma unroll 4
        for (int ks = 0; ks < 16; ks++) {
            const uint32_t kb = ks * 32;               // 16 bf16 = 32 bytes
            uint32_t bhf[4][2], blf[4][2];
            #pragma unroll
            for (int nt = 0; nt < 4; nt++) {
                ldsm2(bhf[nt][0], bhf[nt][1], b_base[nt] + kb);
                ldsm2(blf[nt][0], blf[nt][1], b_base[nt] + BDL + kb);
            }
            uint32_t ahf[2][4], alf[2][4];
            #pragma unroll
            for (int mt = 0; mt < 2; mt++) {
                ldsm4(ahf[mt][0], ahf[mt][1], ahf[mt][2], ahf[mt][3], a_base[mt] + kb);
                ldsm4(alf[mt][0], alf[mt][1], alf[mt][2], alf[mt][3],
                      a_base[mt] + ADL + kb);
            }
            #pragma unroll
            for (int mt = 0; mt < 2; mt++)
                #pragma unroll
                for (int nt = 0; nt < 4; nt++)
                    mma16816(acc[mt][nt], ahf[mt], bhf[nt]);
            #pragma unroll
            for (int mt = 0; mt < 2; mt++)
                #pragma unroll
                for (int nt = 0; nt < 4; nt++)
                    mma16816(acc[mt][nt], ahf[mt], blf[nt]);
            #pragma unroll
            for (int mt = 0; mt < 2; mt++)
                #pragma unroll
                for (int nt = 0; nt < 4; nt++)
                    mma16816(acc[mt][nt], alf[mt], bhf[nt]);
        }

        // ---- epilogue: bias + store ----
        const int gid = lane >> 2, tig = lane & 3;
        #pragma unroll
        for (int mt = 0; mt < 2; mt++) {
            const int r0 = m0 + wm * 32 + mt * 16 + gid;
            #pragma unroll
            for (int nt = 0; nt < 4; nt++) {
                const int cl = wn * 32 + nt * 8 + tig * 2;
                float b0 = biasS[cl], b1 = biasS[cl + 1];
                float* d0 = &g_xp[(size_t)r0 * 1536 + n0 + cl];
                float* d1 = &g_xp[(size_t)(r0 + 8) * 1536 + n0 + cl];
                *(float2*)d0 = make_float2(acc[mt][nt][0] + b0, acc[mt][nt][1] + b1);
                *(float2*)d1 = make_float2(acc[mt][nt][2] + b0, acc[mt][nt][3] + b1);
            }
        }
    }
}

// ============================================================================
// Recurrence v8 (verified 7925us) — UNCHANGED.
// ============================================================================
#define HSTR 516

__global__ void __launch_bounds__(512, 1) recur_kernel(
    const float* __restrict__ h_in,
    const float* __restrict__ Wc, const float* __restrict__ Wa,
    float* __restrict__ out)
{
    extern __shared__ float sm[];
    float* Ws  = sm;
    float* Hs  = sm + 32768;
    float* Red = sm + 32768 + 16512;
    ulonglong2* RedU = (ulonglong2*)Red;

    const int ct = blockIdx.x;
    const int jt = ct & 15, bt = ct >> 4;
    const int j0 = jt * 32, b0 = bt * 32;
    const int tid = threadIdx.x;
    const int w = tid >> 5, lane = tid & 31;
    const int ks = w >> 1, jh = w & 1;
    const int jg = lane >> 3;
    const int bl = lane & 7;
    const int kw0 = ks * 64;
    const int jwl = jh * 16 + jg * 4;

    const int cb  = tid >> 4;
    const int jp  = tid & 15;
    const int cjh = jp >> 3;
    const int cjg = (jp >> 1) & 3;
    const int cje = (jp & 1) * 2;
    const int ci  = cb >> 3, cbl = cb & 7;
    const int rbase = (((cjh * 8 + ci) * 32 + cbl * 4 + cjg) << 2) + cje;

    const int ksm = ks & 3;
    const int pbase = ((ksm * 2 + jh) * 8) * 32 + bl * 4 + jg;

    for (int idx = tid; idx < 32 * 128; idx += 512) {
        int j = idx >> 7, k = (idx & 127) << 2;
        float4 wc = __ldcg((const float4*)&Wc[(size_t)(j0 + j) * HID + k]);
        float4 wa = __ldcg((const float4*)&Wa[(size_t)(j0 + j) * HID + k]);
        Ws[(k + 0) * 64 + j] = wc.x; Ws[(k + 1) * 64 + j] = wc.y;
        Ws[(k + 2) * 64 + j] = wc.z; Ws[(k + 3) * 64 + j] = wc.w;
        Ws[(k + 0) * 64 + 32 + j] = wa.x; Ws[(k + 1) * 64 + 32 + j] = wa.y;
        Ws[(k + 2) * 64 + 32 + j] = wa.z; Ws[(k + 3) * 64 + 32 + j] = wa.w;
    }

    unsigned* cnt = &g_cnt[bt * 32];
    unsigned* gen = &g_gen[bt * 32];
    __shared__ unsigned s_g0;
    if (tid == 0) s_g0 = *gen;
    __syncthreads();
    const unsigned g0 = s_g0;

    float2 xc, xa, xh;
    {
        const size_t crow0 = (size_t)0 * BATCH + b0 + cb;
        const float* xpb = &g_xp[crow0 * 1536 + j0 + jp * 2];
        xc = __ldcg((const float2*)(xpb));
        xa = __ldcg((const float2*)(xpb + 512));
        xh = __ldcg((const float2*)(xpb + 1024));
    }

    for (int t = 0; t < SEQ; t++) {
        const float* __restrict__ hsrc = (t == 0) ? h_in : g_h[t & 1];
        for (int i = tid; i < 32 * 128; i += 512) {
            int r = i >> 7, c = (i & 127) << 2;
            *(float4*)&Hs[r * HSTR + c] =
                __ldcg((const float4*)&hsrc[(size_t)(b0 + r) * HID + c]);
        }
        __syncthreads();

        u64 acc[2][4][2];
        #pragma unroll
        for (int m = 0; m < 2; m++)
            #pragma unroll
            for (int i = 0; i < 4; i++) { acc[m][i][0] = 0ull; acc[m][i][1] = 0ull; }

        #pragma unroll 2
        for (int k4 = 0; k4 < 16; k4++) {
            const int kk = kw0 + k4 * 4;
            float4 hv[4];
            #pragma unroll
            for (int i = 0; i < 4; i++)
                hv[i] = *(const float4*)&Hs[(bl + 8 * i) * HSTR + kk];
            #pragma unroll
            for (int q = 0; q < 4; q++) {
                const float* wr = &Ws[(kk + q) * 64 + jwl];
                ulonglong2 wc = *(const ulonglong2*)wr;
                ulonglong2 wa = *(const ulonglong2*)(wr + 32);
                #pragma unroll
                for (int i = 0; i < 4; i++) {
                    float hq = (q == 0) ? hv[i].x : (q == 1) ? hv[i].y
                             : (q == 2) ? hv[i].z : hv[i].w;
                    u64 hd = dup2(hq);
                    fma2(acc[0][i][0], hd, wc.x); fma2(acc[0][i][1], hd, wc.y);
                    fma2(acc[1][i][0], hd, wa.x); fma2(acc[1][i][1], hd, wa.y);
                }
            }
        }

        if (ks < 4) {
            #pragma unroll
            for (int m = 0; m < 2; m++)
                #pragma unroll
                for (int i = 0; i < 4; i++)
                    RedU[pbase + (m * 4 + i) * 32] =
                        make_ulonglong2(acc[m][i][0], acc[m][i][1]);
        }
        __syncthreads();
        if (ks >= 4) {
            #pragma unroll
            for (int m = 0; m < 2; m++)
                #pragma unroll
                for (int i = 0; i < 4; i++) {
                    const int idx = pbase + (m * 4 + i) * 32;
                    ulonglong2 v = RedU[idx];
                    add2(acc[m][i][0], v.x); add2(acc[m][i][1], v.y);
                    RedU[idx] = make_ulonglong2(acc[m][i][0], acc[m][i][1]);
                }
        }
        __syncthreads();

        {
            float2 hc = make_float2(0.f, 0.f), ha = make_float2(0.f, 0.f);
            #pragma unroll
            for (int r = 0; r < 4; r++) {
                float2 vc = *(const float2*)&Red[rbase + r * 2048];
                float2 va = *(const float2*)&Red[rbase + r * 2048 + 512];
                hc.x += vc.x; hc.y += vc.y;
                ha.x += va.x; ha.y += va.y;
            }
            float2 hp = *(const float2*)&Hs[cb * HSTR + j0 + jp * 2];
            const size_t crow = (size_t)t * BATCH + b0 + cb;

            float r0, r1;
            {
                float cg = sig_f(xc.x + hc.x);
                float ag = 1.0f + tanh_f(xa.x + ha.x);
                r0 = cg * hp.x + (1.0f - cg) * tanh_f(xh.x + ag * hp.x);
            }
            {
                float cg = sig_f(xc.y + hc.y);
                float ag = 1.0f + tanh_f(xa.y + ha.y);
                r1 = cg * hp.y + (1.0f - cg) * tanh_f(xh.y + ag * hp.y);
            }
            float2 rv = make_float2(r0, r1);
            *(float2*)&out[crow * HID + j0 + jp * 2] = rv;
            *(float2*)&g_h[(t + 1) & 1][(size_t)(b0 + cb) * HID + j0 + jp * 2] = rv;
            if (t == SEQ - 1)
                *(float2*)&out[(size_t)SEQ * BATCH * HID +
                               (size_t)(b0 + cb) * HID + j0 + jp * 2] = rv;
        }

        if (t < SEQ - 1) {
            const size_t nrow = (size_t)(t + 1) * BATCH + b0 + cb;
            const float* nxpb = &g_xp[nrow * 1536 + j0 + jp * 2];
            xc = __ldcg((const float2*)(nxpb));
            xa = __ldcg((const float2*)(nxpb + 512));
            xh = __ldcg((const float2*)(nxpb + 1024));

            __syncthreads();
            if (tid == 0) {
                __threadfence();
                const unsigned target = g0 + (unsigned)t + 1u;
                if (atomicAdd(cnt, 1u) == 15u) {
                    atomicExch(cnt, 0u);
                    __threadfence();
                    st_rel(gen, target);
                } else {
                    while (ld_acq(gen) != target) { }
                }
            }
            __syncthreads();
        }
    }
}

// ============================================================================
extern "C" void kernel_launch(void* const* d_in, const int* in_sizes, int n_in,
                              void* d_out, int out_size)
{
    const float* X  = (const float*)d_in[0];
    const float* h0 = (const float*)d_in[1];
    const float* Uc = (const float*)d_in[2];
    const float* Wc = (const float*)d_in[3];
    const float* bc = (const float*)d_in[4];
    const float* Ua = (const float*)d_in[5];
    const float* Wa = (const float*)d_in[6];
    const float* ba = (const float*)d_in[7];
    const float* Uh = (const float*)d_in[8];
    const float* bh = (const float*)d_in[9];
    float* out = (float*)d_out;

    cudaFuncSetAttribute(proj_mma_kernel, cudaFuncAttributeMaxDynamicSharedMemorySize,
                         SM_PROJ_TOT);
    const size_t shmem = (size_t)(32768 + 16512 + 8192) * sizeof(float); // 229888 B
    cudaFuncSetAttribute(recur_kernel, cudaFuncAttributeMaxDynamicSharedMemorySize,
                         (int)shmem);

    xsplit_kernel<<<4096, 256>>>(X);
    usplit_kernel<<<384, 256>>>(Uc, Ua, Uh);
    dim3 pg(24, 128);
    proj_mma_kernel<<<pg, 256, SM_PROJ_TOT>>>(bc, ba, bh);
    recur_kernel<<<128, 512, shmem>>>(h0, Wc, Wa, out);
}

// round 12
// speedup vs baseline: 2.6232x; 1.3993x over previous
#include <cuda_runtime.h>
#include <cuda_bf16.h>
#include <cstddef>
#include <cstdint>
#include <math.h>

#define SEQ   512
#define BATCH 256
#define INP   256
#define HID   512

typedef unsigned long long u64;

// ---------- packed f32x2 helpers ----------
__device__ __forceinline__ u64 dup2(float x) {
    u64 r; asm("mov.b64 %0,{%1,%1};" : "=l"(r) : "f"(x)); return r;
}
__device__ __forceinline__ void fma2(u64& d, u64 a, u64 b) {
    asm("fma.rn.f32x2 %0,%1,%2,%0;" : "+l"(d) : "l"(a), "l"(b));
}
__device__ __forceinline__ float2 upk(u64 v) {
    float2 f; asm("mov.b64 {%0,%1},%2;" : "=f"(f.x), "=f"(f.y) : "l"(v)); return f;
}

// ---------- sync helpers ----------
__device__ __forceinline__ unsigned ld_acq(const unsigned* p) {
    unsigned v;
    asm volatile("ld.acquire.gpu.global.b32 %0,[%1];" : "=r"(v) : "l"(p) : "memory");
    return v;
}
__device__ __forceinline__ void st_rel(unsigned* p, unsigned v) {
    asm volatile("st.release.gpu.global.b32 [%0],%1;" :: "l"(p), "r"(v) : "memory");
}

// ---------- fast activations ----------
__device__ __forceinline__ float sig_f(float z) {
    return __fdividef(1.0f, 1.0f + __expf(-z));
}
__device__ __forceinline__ float tanh_f(float z) {
    return 1.0f - __fdividef(2.0f, __expf(2.0f * z) + 1.0f);
}

// ---------- scratch ----------
__device__ float g_xp[(size_t)SEQ * BATCH * 3 * HID];
__device__ float g_h[2][BATCH * HID];
__device__ unsigned g_cnt[8 * 32];
__device__ unsigned g_gen[8 * 32];
__device__ __nv_bfloat16 g_xh[(size_t)SEQ * BATCH * INP];
__device__ __nv_bfloat16 g_xl[(size_t)SEQ * BATCH * INP];
__device__ __nv_bfloat16 g_uh[3 * HID * INP];
__device__ __nv_bfloat16 g_ul[3 * HID * INP];

// ---------- split helpers ----------
__device__ __forceinline__ uint32_t pck(__nv_bfloat16 a, __nv_bfloat16 b) {
    return (uint32_t)__bfloat16_as_ushort(a) | ((uint32_t)__bfloat16_as_ushort(b) << 16);
}
__device__ __forceinline__ void split4(float4 v, uint2& hi, uint2& lo) {
    __nv_bfloat16 h0 = __float2bfloat16_rn(v.x), h1 = __float2bfloat16_rn(v.y);
    __nv_bfloat16 h2 = __float2bfloat16_rn(v.z), h3 = __float2bfloat16_rn(v.w);
    __nv_bfloat16 l0 = __float2bfloat16_rn(v.x - __bfloat162float(h0));
    __nv_bfloat16 l1 = __float2bfloat16_rn(v.y - __bfloat162float(h1));
    __nv_bfloat16 l2 = __float2bfloat16_rn(v.z - __bfloat162float(h2));
    __nv_bfloat16 l3 = __float2bfloat16_rn(v.w - __bfloat162float(h3));
    hi = make_uint2(pck(h0, h1), pck(h2, h3));
    lo = make_uint2(pck(l0, l1), pck(l2, l3));
}

__global__ void __launch_bounds__(256) xsplit_kernel(const float* __restrict__ X) {
    const size_t total = (size_t)SEQ * BATCH * INP / 4;
    for (size_t f4 = (size_t)blockIdx.x * 256 + threadIdx.x; f4 < total;
         f4 += (size_t)gridDim.x * 256) {
        float4 v = __ldcg((const float4*)X + f4);
        uint2 hi, lo; split4(v, hi, lo);
        ((uint2*)g_xh)[f4] = hi;
        ((uint2*)g_xl)[f4] = lo;
    }
}

__global__ void __launch_bounds__(256) usplit_kernel(
    const float* __restrict__ Uc, const float* __restrict__ Ua,
    const float* __restrict__ Uh)
{
    const int mat = blockIdx.x >> 7;
    const int f4 = (blockIdx.x & 127) * 256 + threadIdx.x;
    const float* src = (mat == 0) ? Uc : (mat == 1 ? Ua : Uh);
    float4 v = __ldcg((const float4*)src + f4);
    uint2 hi, lo; split4(v, hi, lo);
    ((uint2*)g_uh)[mat * 32768 + f4] = hi;
    ((uint2*)g_ul)[mat * 32768 + f4] = lo;
}

// ---------- mma / ldmatrix ----------
__device__ __forceinline__ uint32_t smem_u32(const void* p) {
    uint32_t a;
    asm("{ .reg .u64 t; cvta.to.shared.u64 t,%1; cvt.u32.u64 %0,t; }" : "=r"(a) : "l"(p));
    return a;
}
__device__ __forceinline__ void ldsm4(uint32_t& r0, uint32_t& r1, uint32_t& r2,
                                      uint32_t& r3, uint32_t a) {
    asm volatile("ldmatrix.sync.aligned.m8n8.x4.shared.b16 {%0,%1,%2,%3},[%4];"
                 : "=r"(r0), "=r"(r1), "=r"(r2), "=r"(r3) : "r"(a));
}
__device__ __forceinline__ void ldsm2(uint32_t& r0, uint32_t& r1, uint32_t a) {
    asm volatile("ldmatrix.sync.aligned.m8n8.x2.shared.b16 {%0,%1},[%2];"
                 : "=r"(r0), "=r"(r1) : "r"(a));
}
__device__ __forceinline__ void mma16816(float* d, const uint32_t* a, const uint32_t* b) {
    asm volatile(
        "mma.sync.aligned.m16n8k16.row.col.f32.bf16.bf16.f32 "
        "{%0,%1,%2,%3},{%4,%5,%6,%7},{%8,%9},{%0,%1,%2,%3};"
        : "+f"(d[0]), "+f"(d[1]), "+f"(d[2]), "+f"(d[3])
        : "r"(a[0]), "r"(a[1]), "r"(a[2]), "r"(a[3]), "r"(b[0]), "r"(b[1]));
}

// ======================= projection (unchanged from R11) =====================
#define PSTR 528
#define SM_PBIAS 0
#define SM_BH 1024
#define SM_BL (SM_BH + 64 * PSTR)
#define SM_AH (SM_BL + 64 * PSTR)
#define SM_AL (SM_AH + 128 * PSTR)
#define SM_PROJ_TOT (SM_AL + 128 * PSTR)

__global__ void __launch_bounds__(256, 1) proj_mma_kernel(
    const float* __restrict__ bc, const float* __restrict__ ba,
    const float* __restrict__ bh)
{
    extern __shared__ __align__(1024) char smem[];
    const uint32_t sb = smem_u32(smem);
    const int tid = threadIdx.x;
    const int wid = tid >> 5;
    const int lane = tid & 31;

    const int n0 = blockIdx.x * 64;
    const int region = n0 >> 9;
    const int nl0 = n0 & 511;
    const float* __restrict__ bias = (region == 0) ? bc : (region == 1 ? ba : bh);
    float* biasS = (float*)(smem + SM_PBIAS);
    if (tid < 64) biasS[tid] = bias[nl0 + tid];

    const __nv_bfloat16* ubase_h = g_uh + (size_t)region * HID * INP;
    const __nv_bfloat16* ubase_l = g_ul + (size_t)region * HID * INP;
    for (int idx = tid; idx < 4096; idx += 256) {
        int sel = idx >> 11;
        int r = (idx >> 5) & 63, c = idx & 31;
        const __nv_bfloat16* src = (sel ? ubase_l : ubase_h) + (size_t)(nl0 + r) * INP;
        uint4 v = ((const uint4*)src)[c];
        *(uint4*)(smem + (sel ? SM_BL : SM_BH) + r * PSTR + c * 16) = v;
    }

    const int wm = wid & 3, wn = wid >> 2;
    const int msel = lane >> 3;
    const int arow = (msel & 1) * 8 + (lane & 7);
    const int acol16 = (msel >> 1);
    uint32_t a_base[2];
    #pragma unroll
    for (int mt = 0; mt < 2; mt++)
        a_base[mt] = sb + SM_AH + (wm * 32 + mt * 16 + arow) * PSTR + acol16 * 16;
    uint32_t b_base[4];
    #pragma unroll
    for (int nt = 0; nt < 4; nt++)
        b_base[nt] = sb + SM_BH + (wn * 32 + nt * 8 + (lane & 7)) * PSTR
                   + ((lane >> 3) & 1) * 16;
    const uint32_t ADL = SM_AL - SM_AH;
    const uint32_t BDL = SM_BL - SM_BH;

    for (int i = 0; i < 8; i++) {
        const int m0 = (blockIdx.y * 8 + i) * 128;
        __syncthreads();

        for (int idx = tid; idx < 8192; idx += 256) {
            int sel = idx >> 12;
            int r = (idx >> 5) & 127, c = idx & 31;
            const __nv_bfloat16* src = (sel ? g_xl : g_xh) + (size_t)(m0 + r) * INP;
            uint4 v = __ldcg((const uint4*)src + c);
            *(uint4*)(smem + (sel ? SM_AL : SM_AH) + r * PSTR + c * 16) = v;
        }
        __syncthreads();

        float acc[2][4][4];
        #pragma unroll
        for (int mt = 0; mt < 2; mt++)
            #pragma unroll
            for (int nt = 0; nt < 4; nt++)
                #pragma unroll
                for (int q = 0; q < 4; q++) acc[mt][nt][q] = 0.0f;

        #pragma unroll 4
        for (int ks = 0; ks < 16; ks++) {
            const uint32_t kb = ks * 32;
            uint32_t bhf[4][2], blf[4][2];
            #pragma unroll
            for (int nt = 0; nt < 4; nt++) {
                ldsm2(bhf[nt][0], bhf[nt][1], b_base[nt] + kb);
                ldsm2(blf[nt][0], blf[nt][1], b_base[nt] + BDL + kb);
            }
            uint32_t ahf[2][4], alf[2][4];
            #pragma unroll
            for (int mt = 0; mt < 2; mt++) {
                ldsm4(ahf[mt][0], ahf[mt][1], ahf[mt][2], ahf[mt][3], a_base[mt] + kb);
                ldsm4(alf[mt][0], alf[mt][1], alf[mt][2], alf[mt][3],
                      a_base[mt] + ADL + kb);
            }
            #pragma unroll
            for (int mt = 0; mt < 2; mt++)
                #pragma unroll
                for (int nt = 0; nt < 4; nt++)
                    mma16816(acc[mt][nt], ahf[mt], bhf[nt]);
            #pragma unroll
            for (int mt = 0; mt < 2; mt++)
                #pragma unroll
                for (int nt = 0; nt < 4; nt++)
                    mma16816(acc[mt][nt], ahf[mt], blf[nt]);
            #pragma unroll
            for (int mt = 0; mt < 2; mt++)
                #pragma unroll
                for (int nt = 0; nt < 4; nt++)
                    mma16816(acc[mt][nt], alf[mt], bhf[nt]);
        }

        const int gid = lane >> 2, tig = lane & 3;
        #pragma unroll
        for (int mt = 0; mt < 2; mt++) {
            const int r0 = m0 + wm * 32 + mt * 16 + gid;
            #pragma unroll
            for (int nt = 0; nt < 4; nt++) {
                const int cl = wn * 32 + nt * 8 + tig * 2;
                float b0 = biasS[cl], b1 = biasS[cl + 1];
                float* d0 = &g_xp[(size_t)r0 * 1536 + n0 + cl];
                float* d1 = &g_xp[(size_t)(r0 + 8) * 1536 + n0 + cl];
                *(float2*)d0 = make_float2(acc[mt][nt][0] + b0, acc[mt][nt][1] + b1);
                *(float2*)d1 = make_float2(acc[mt][nt][2] + b0, acc[mt][nt][3] + b1);
            }
        }
    }
}

// ======================= recurrence v9: HMMA matvec ==========================
// R8 skeleton (staging/syncs/barrier/consumer mapping/stores identical) with
// the fp32 fma2 matvec replaced by split-bf16 ldmatrix+mma (validated in proj).
// Warp = (ks in 4) x (mat in 2) x (mt in 2): m16(b) x 32j over 128k slice.
// SMEM bytes: W hi/lo (2 mats) + h hi/lo, rows padded to 1040B; Red 16KB.
#define WSTR   1040
#define SM_WHC 0
#define SM_WHA 66560                      // WHC block is hi(33280)+lo(33280)
#define SM_HH  133120
#define SM_HL  166400
#define SM_RED 199680
#define SM_REC_TOT 216064
#define LODELTA 33280                     // hi -> lo within each block

__global__ void __launch_bounds__(512, 1) recur_kernel(
    const float* __restrict__ h_in,
    const float* __restrict__ Wc, const float* __restrict__ Wa,
    float* __restrict__ out)
{
    extern __shared__ __align__(1024) char smem[];
    const uint32_t sb = smem_u32(smem);
    float4* RedF4 = (float4*)(smem + SM_RED);
    const float2* RedF2 = (const float2*)(smem + SM_RED);

    const int ct = blockIdx.x;
    const int jt = ct & 15, bt = ct >> 4;
    const int j0 = jt * 32, b0 = bt * 32;
    const int tid = threadIdx.x;
    const int w = tid >> 5, lane = tid & 31;
    const int ks = w & 3, mat = (w >> 2) & 1, mt = w >> 3;

    // ldmatrix bases (scheme identical to proj kernel)
    const int msel = lane >> 3;
    const uint32_t abase = sb + SM_HH +
        (mt * 16 + (msel & 1) * 8 + (lane & 7)) * WSTR + (msel >> 1) * 16;
    uint32_t b_base[4];
    #pragma unroll
    for (int nt = 0; nt < 4; nt++)
        b_base[nt] = sb + (mat ? SM_WHA : SM_WHC) +
            (nt * 8 + (lane & 7)) * WSTR + ((lane >> 3) & 1) * 16;

    // consumer mapping (identical to R8): cb = tid>>4, jp = tid&15
    const int cb = tid >> 4, jp = tid & 15;
    const int cmt = cb >> 4, cqh = (cb >> 3) & 1, cgid = cb & 7;
    const int clane = cgid * 4 + (jp & 3);
    const int cntc = jp >> 2;

    // ---- one-time: stage W hi/lo (both mats), [j][k] bf16 rows ----
    for (int idx = tid; idx < 8192; idx += 512) {
        int m = idx >> 12;                 // 0=Wc 1=Wa
        int j = (idx >> 7) & 31;
        int kc = idx & 127;                // float4 chunk along k
        const float* src = (m ? Wa : Wc) + (size_t)(j0 + j) * HID + kc * 4;
        float4 v = __ldcg((const float4*)src);
        uint2 hi, lo; split4(v, hi, lo);
        char* bp = smem + (m ? SM_WHA : SM_WHC) + j * WSTR + kc * 8;
        *(uint2*)bp = hi;
        *(uint2*)(bp + LODELTA) = lo;
    }

    unsigned* cnt = &g_cnt[bt * 32];
    unsigned* gen = &g_gen[bt * 32];
    __shared__ unsigned s_g0;
    if (tid == 0) s_g0 = *gen;
    __syncthreads();
    const unsigned g0 = s_g0;

    // xp prefetch t=0 (consumer-mapped)
    float2 xc, xa, xh;
    {
        const size_t crow0 = (size_t)b0 + cb;
        const float* xpb = &g_xp[crow0 * 1536 + j0 + jp * 2];
        xc = __ldcg((const float2*)(xpb));
        xa = __ldcg((const float2*)(xpb + 512));
        xh = __ldcg((const float2*)(xpb + 1024));
    }

    for (int t = 0; t < SEQ; t++) {
        // ---- stage h tile, splitting fp32 -> bf16 hi/lo ----
        const float* __restrict__ hsrc = (t == 0) ? h_in : g_h[t & 1];
        for (int i = tid; i < 32 * 128; i += 512) {
            int r = i >> 7, kc = i & 127;
            float4 v = __ldcg((const float4*)&hsrc[(size_t)(b0 + r) * HID + kc * 4]);
            uint2 hi, lo; split4(v, hi, lo);
            char* bp = smem + SM_HH + r * WSTR + kc * 8;
            *(uint2*)bp = hi;
            *(uint2*)(bp + LODELTA) = lo;
        }
        __syncthreads();

        // ---- HMMA matvec: m16 x 32j over 128k slice, split 3 products ----
        float acc[4][4];
        #pragma unroll
        for (int nt = 0; nt < 4; nt++)
            #pragma unroll
            for (int q = 0; q < 4; q++) acc[nt][q] = 0.0f;

        #pragma unroll
        for (int kstep = 0; kstep < 8; kstep++) {
            const uint32_t kb = ks * 256 + kstep * 32;
            uint32_t ahf[4], alf[4];
            ldsm4(ahf[0], ahf[1], ahf[2], ahf[3], abase + kb);
            ldsm4(alf[0], alf[1], alf[2], alf[3], abase + LODELTA + kb);
            uint32_t bhf[4][2], blf[4][2];
            #pragma unroll
            for (int nt = 0; nt < 4; nt++) {
                ldsm2(bhf[nt][0], bhf[nt][1], b_base[nt] + kb);
                ldsm2(blf[nt][0], blf[nt][1], b_base[nt] + LODELTA + kb);
            }
            #pragma unroll
            for (int nt = 0; nt < 4; nt++) {
                mma16816(acc[nt], ahf, bhf[nt]);
                mma16816(acc[nt], ahf, blf[nt]);
                mma16816(acc[nt], alf, bhf[nt]);
            }
        }

        // ---- reduction over 4 k-slices: 2 store, 2 add (R8 pattern) ----
        const int rgbase = (mat * 2 + mt) * 2;
        if (ks < 2) {
            #pragma unroll
            for (int nt = 0; nt < 4; nt++)
                RedF4[(rgbase + ks) * 128 + lane * 4 + nt] =
                    make_float4(acc[nt][0], acc[nt][1], acc[nt][2], acc[nt][3]);
        }
        __syncthreads();
        if (ks >= 2) {
            #pragma unroll
            for (int nt = 0; nt < 4; nt++) {
                const int idx = (rgbase + ks - 2) * 128 + lane * 4 + nt;
                float4 v = RedF4[idx];
                v.x += acc[nt][0]; v.y += acc[nt][1];
                v.z += acc[nt][2]; v.w += acc[nt][3];
                RedF4[idx] = v;
            }
        }
        __syncthreads();

        // ---- consumer: gather hc/ha, reconstruct hp, gated epilogue ----
        {
            const int f4c = cmt * 2 * 128 + clane * 4 + cntc;          // mat 0, r 0
            const int f4a = (cmt * 2 + 4) * 128 + clane * 4 + cntc;    // mat 1, r 0
            float2 c0 = RedF2[(f4c) * 2 + cqh];
            float2 c1 = RedF2[(f4c + 128) * 2 + cqh];
            float2 a0 = RedF2[(f4a) * 2 + cqh];
            float2 a1 = RedF2[(f4a + 128) * 2 + cqh];
            float2 hc = make_float2(c0.x + c1.x, c0.y + c1.y);
            float2 ha = make_float2(a0.x + a1.x, a0.y + a1.y);

            // hp = hi + lo (error ~2^-18)
            const uint32_t hb = *(const uint32_t*)(smem + SM_HH + cb * WSTR +
                                                   (j0 + jp * 2) * 2);
            const uint32_t lb = *(const uint32_t*)(smem + SM_HL + cb * WSTR +
                                                   (j0 + jp * 2) * 2);
            float hp0 = __bfloat162float(__ushort_as_bfloat16((unsigned short)(hb & 0xFFFF)))
                      + __bfloat162float(__ushort_as_bfloat16((unsigned short)(lb & 0xFFFF)));
            float hp1 = __bfloat162float(__ushort_as_bfloat16((unsigned short)(hb >> 16)))
                      + __bfloat162float(__ushort_as_bfloat16((unsigned short)(lb >> 16)));

            const size_t crow = (size_t)t * BATCH + b0 + cb;
            float r0, r1;
            {
                float cg = sig_f(xc.x + hc.x);
                float ag = 1.0f + tanh_f(xa.x + ha.x);
                r0 = cg * hp0 + (1.0f - cg) * tanh_f(xh.x + ag * hp0);
            }
            {
                float cg = sig_f(xc.y + hc.y);
                float ag = 1.0f + tanh_f(xa.y + ha.y);
                r1 = cg * hp1 + (1.0f - cg) * tanh_f(xh.y + ag * hp1);
            }
            float2 rv = make_float2(r0, r1);
            *(float2*)&out[crow * HID + j0 + jp * 2] = rv;
            *(float2*)&g_h[(t + 1) & 1][(size_t)(b0 + cb) * HID + j0 + jp * 2] = rv;
            if (t == SEQ - 1)
                *(float2*)&out[(size_t)SEQ * BATCH * HID +
                               (size_t)(b0 + cb) * HID + j0 + jp * 2] = rv;
        }

        // ---- prefetch next xp, then counting barrier (identical to R8) ----
        if (t < SEQ - 1) {
            const size_t nrow = (size_t)(t + 1) * BATCH + b0 + cb;
            const float* nxpb = &g_xp[nrow * 1536 + j0 + jp * 2];
            xc = __ldcg((const float2*)(nxpb));
            xa = __ldcg((const float2*)(nxpb + 512));
            xh = __ldcg((const float2*)(nxpb + 1024));

            __syncthreads();
            if (tid == 0) {
                __threadfence();
                const unsigned target = g0 + (unsigned)t + 1u;
                if (atomicAdd(cnt, 1u) == 15u) {
                    atomicExch(cnt, 0u);
                    __threadfence();
                    st_rel(gen, target);
                } else {
                    while (ld_acq(gen) != target) { }
                }
            }
            __syncthreads();
        }
    }
}

// ============================================================================
extern "C" void kernel_launch(void* const* d_in, const int* in_sizes, int n_in,
                              void* d_out, int out_size)
{
    const float* X  = (const float*)d_in[0];
    const float* h0 = (const float*)d_in[1];
    const float* Uc = (const float*)d_in[2];
    const float* Wc = (const float*)d_in[3];
    const float* bc = (const float*)d_in[4];
    const float* Ua = (const float*)d_in[5];
    const float* Wa = (const float*)d_in[6];
    const float* ba = (const float*)d_in[7];
    const float* Uh = (const float*)d_in[8];
    const float* bh = (const float*)d_in[9];
    float* out = (float*)d_out;

    cudaFuncSetAttribute(proj_mma_kernel, cudaFuncAttributeMaxDynamicSharedMemorySize,
                         SM_PROJ_TOT);
    cudaFuncSetAttribute(recur_kernel, cudaFuncAttributeMaxDynamicSharedMemorySize,
                         SM_REC_TOT);

    xsplit_kernel<<<4096, 256>>>(X);
    usplit_kernel<<<384, 256>>>(Uc, Ua, Uh);
    dim3 pg(24, 128);
    proj_mma_kernel<<<pg, 256, SM_PROJ_TOT>>>(bc, ba, bh);
    recur_kernel<<<128, 512, SM_REC_TOT>>>(h0, Wc, Wa, out);
}

// round 13
// speedup vs baseline: 2.7316x; 1.0413x over previous
#include <cuda_runtime.h>
#include <cuda_bf16.h>
#include <cstddef>
#include <cstdint>
#include <math.h>

#define SEQ   512
#define BATCH 256
#define INP   256
#define HID   512

typedef unsigned long long u64;

// ---------- sync helpers ----------
__device__ __forceinline__ unsigned ld_acq(const unsigned* p) {
    unsigned v;
    asm volatile("ld.acquire.gpu.global.b32 %0,[%1];" : "=r"(v) : "l"(p) : "memory");
    return v;
}
__device__ __forceinline__ void st_rel(unsigned* p, unsigned v) {
    asm volatile("st.release.gpu.global.b32 [%0],%1;" :: "l"(p), "r"(v) : "memory");
}

// ---------- fast activations ----------
__device__ __forceinline__ float sig_f(float z) {
    return __fdividef(1.0f, 1.0f + __expf(-z));
}
__device__ __forceinline__ float tanh_f(float z) {
    return 1.0f - __fdividef(2.0f, __expf(2.0f * z) + 1.0f);
}

// ---------- scratch ----------
__device__ float g_xp[(size_t)SEQ * BATCH * 3 * HID];
__device__ uint32_t g_hb[2][2][BATCH * HID / 2];   // [buf][plane hi/lo][b*256 + j/2]
__device__ unsigned g_cnt[8 * 32];
__device__ unsigned g_gen[8 * 32];
__device__ __nv_bfloat16 g_xh[(size_t)SEQ * BATCH * INP];
__device__ __nv_bfloat16 g_xl[(size_t)SEQ * BATCH * INP];
__device__ __nv_bfloat16 g_uh[3 * HID * INP];
__device__ __nv_bfloat16 g_ul[3 * HID * INP];

// ---------- split helpers ----------
__device__ __forceinline__ uint32_t pck(__nv_bfloat16 a, __nv_bfloat16 b) {
    return (uint32_t)__bfloat16_as_ushort(a) | ((uint32_t)__bfloat16_as_ushort(b) << 16);
}
__device__ __forceinline__ void split4(float4 v, uint2& hi, uint2& lo) {
    __nv_bfloat16 h0 = __float2bfloat16_rn(v.x), h1 = __float2bfloat16_rn(v.y);
    __nv_bfloat16 h2 = __float2bfloat16_rn(v.z), h3 = __float2bfloat16_rn(v.w);
    __nv_bfloat16 l0 = __float2bfloat16_rn(v.x - __bfloat162float(h0));
    __nv_bfloat16 l1 = __float2bfloat16_rn(v.y - __bfloat162float(h1));
    __nv_bfloat16 l2 = __float2bfloat16_rn(v.z - __bfloat162float(h2));
    __nv_bfloat16 l3 = __float2bfloat16_rn(v.w - __bfloat162float(h3));
    hi = make_uint2(pck(h0, h1), pck(h2, h3));
    lo = make_uint2(pck(l0, l1), pck(l2, l3));
}

__global__ void __launch_bounds__(256) xsplit_kernel(const float* __restrict__ X) {
    const size_t total = (size_t)SEQ * BATCH * INP / 4;
    for (size_t f4 = (size_t)blockIdx.x * 256 + threadIdx.x; f4 < total;
         f4 += (size_t)gridDim.x * 256) {
        float4 v = __ldcg((const float4*)X + f4);
        uint2 hi, lo; split4(v, hi, lo);
        ((uint2*)g_xh)[f4] = hi;
        ((uint2*)g_xl)[f4] = lo;
    }
}

__global__ void __launch_bounds__(256) usplit_kernel(
    const float* __restrict__ Uc, const float* __restrict__ Ua,
    const float* __restrict__ Uh)
{
    const int mat = blockIdx.x >> 7;
    const int f4 = (blockIdx.x & 127) * 256 + threadIdx.x;
    const float* src = (mat == 0) ? Uc : (mat == 1 ? Ua : Uh);
    float4 v = __ldcg((const float4*)src + f4);
    uint2 hi, lo; split4(v, hi, lo);
    ((uint2*)g_uh)[mat * 32768 + f4] = hi;
    ((uint2*)g_ul)[mat * 32768 + f4] = lo;
}

// ---------- mma / ldmatrix ----------
__device__ __forceinline__ uint32_t smem_u32(const void* p) {
    uint32_t a;
    asm("{ .reg .u64 t; cvta.to.shared.u64 t,%1; cvt.u32.u64 %0,t; }" : "=r"(a) : "l"(p));
    return a;
}
__device__ __forceinline__ void ldsm4(uint32_t& r0, uint32_t& r1, uint32_t& r2,
                                      uint32_t& r3, uint32_t a) {
    asm volatile("ldmatrix.sync.aligned.m8n8.x4.shared.b16 {%0,%1,%2,%3},[%4];"
                 : "=r"(r0), "=r"(r1), "=r"(r2), "=r"(r3) : "r"(a));
}
__device__ __forceinline__ void ldsm2(uint32_t& r0, uint32_t& r1, uint32_t a) {
    asm volatile("ldmatrix.sync.aligned.m8n8.x2.shared.b16 {%0,%1},[%2];"
                 : "=r"(r0), "=r"(r1) : "r"(a));
}
__device__ __forceinline__ void mma16816(float* d, const uint32_t* a, const uint32_t* b) {
    asm volatile(
        "mma.sync.aligned.m16n8k16.row.col.f32.bf16.bf16.f32 "
        "{%0,%1,%2,%3},{%4,%5,%6,%7},{%8,%9},{%0,%1,%2,%3};"
        : "+f"(d[0]), "+f"(d[1]), "+f"(d[2]), "+f"(d[3])
        : "r"(a[0]), "r"(a[1]), "r"(a[2]), "r"(a[3]), "r"(b[0]), "r"(b[1]));
}

// ======================= projection (unchanged from R11) =====================
#define PSTR 528
#define SM_PBIAS 0
#define SM_BH 1024
#define SM_BL (SM_BH + 64 * PSTR)
#define SM_AH (SM_BL + 64 * PSTR)
#define SM_AL (SM_AH + 128 * PSTR)
#define SM_PROJ_TOT (SM_AL + 128 * PSTR)

__global__ void __launch_bounds__(256, 1) proj_mma_kernel(
    const float* __restrict__ bc, const float* __restrict__ ba,
    const float* __restrict__ bh)
{
    extern __shared__ __align__(1024) char smem[];
    const uint32_t sb = smem_u32(smem);
    const int tid = threadIdx.x;
    const int wid = tid >> 5;
    const int lane = tid & 31;

    const int n0 = blockIdx.x * 64;
    const int region = n0 >> 9;
    const int nl0 = n0 & 511;
    const float* __restrict__ bias = (region == 0) ? bc : (region == 1 ? ba : bh);
    float* biasS = (float*)(smem + SM_PBIAS);
    if (tid < 64) biasS[tid] = bias[nl0 + tid];

    const __nv_bfloat16* ubase_h = g_uh + (size_t)region * HID * INP;
    const __nv_bfloat16* ubase_l = g_ul + (size_t)region * HID * INP;
    for (int idx = tid; idx < 4096; idx += 256) {
        int sel = idx >> 11;
        int r = (idx >> 5) & 63, c = idx & 31;
        const __nv_bfloat16* src = (sel ? ubase_l : ubase_h) + (size_t)(nl0 + r) * INP;
        uint4 v = ((const uint4*)src)[c];
        *(uint4*)(smem + (sel ? SM_BL : SM_BH) + r * PSTR + c * 16) = v;
    }

    const int wm = wid & 3, wn = wid >> 2;
    const int msel = lane >> 3;
    const int arow = (msel & 1) * 8 + (lane & 7);
    const int acol16 = (msel >> 1);
    uint32_t a_base[2];
    #pragma unroll
    for (int mt = 0; mt < 2; mt++)
        a_base[mt] = sb + SM_AH + (wm * 32 + mt * 16 + arow) * PSTR + acol16 * 16;
    uint32_t b_base[4];
    #pragma unroll
    for (int nt = 0; nt < 4; nt++)
        b_base[nt] = sb + SM_BH + (wn * 32 + nt * 8 + (lane & 7)) * PSTR
                   + ((lane >> 3) & 1) * 16;
    const uint32_t ADL = SM_AL - SM_AH;
    const uint32_t BDL = SM_BL - SM_BH;

    for (int i = 0; i < 8; i++) {
        const int m0 = (blockIdx.y * 8 + i) * 128;
        __syncthreads();

        for (int idx = tid; idx < 8192; idx += 256) {
            int sel = idx >> 12;
            int r = (idx >> 5) & 127, c = idx & 31;
            const __nv_bfloat16* src = (sel ? g_xl : g_xh) + (size_t)(m0 + r) * INP;
            uint4 v = __ldcg((const uint4*)src + c);
            *(uint4*)(smem + (sel ? SM_AL : SM_AH) + r * PSTR + c * 16) = v;
        }
        __syncthreads();

        float acc[2][4][4];
        #pragma unroll
        for (int mt = 0; mt < 2; mt++)
            #pragma unroll
            for (int nt = 0; nt < 4; nt++)
                #pragma unroll
                for (int q = 0; q < 4; q++) acc[mt][nt][q] = 0.0f;

        #pragma unroll 4
        for (int ks = 0; ks < 16; ks++) {
            const uint32_t kb = ks * 32;
            uint32_t bhf[4][2], blf[4][2];
            #pragma unroll
            for (int nt = 0; nt < 4; nt++) {
                ldsm2(bhf[nt][0], bhf[nt][1], b_base[nt] + kb);
                ldsm2(blf[nt][0], blf[nt][1], b_base[nt] + BDL + kb);
            }
            uint32_t ahf[2][4], alf[2][4];
            #pragma unroll
            for (int mt = 0; mt < 2; mt++) {
                ldsm4(ahf[mt][0], ahf[mt][1], ahf[mt][2], ahf[mt][3], a_base[mt] + kb);
                ldsm4(alf[mt][0], alf[mt][1], alf[mt][2], alf[mt][3],
                      a_base[mt] + ADL + kb);
            }
            #pragma unroll
            for (int mt = 0; mt < 2; mt++)
                #pragma unroll
                for (int nt = 0; nt < 4; nt++)
                    mma16816(acc[mt][nt], ahf[mt], bhf[nt]);
            #pragma unroll
            for (int mt = 0; mt < 2; mt++)
                #pragma unroll
                for (int nt = 0; nt < 4; nt++)
                    mma16816(acc[mt][nt], ahf[mt], blf[nt]);
            #pragma unroll
            for (int mt = 0; mt < 2; mt++)
                #pragma unroll
                for (int nt = 0; nt < 4; nt++)
                    mma16816(acc[mt][nt], alf[mt], bhf[nt]);
        }

        const int gid = lane >> 2, tig = lane & 3;
        #pragma unroll
        for (int mt = 0; mt < 2; mt++) {
            const int r0 = m0 + wm * 32 + mt * 16 + gid;
            #pragma unroll
            for (int nt = 0; nt < 4; nt++) {
                const int cl = wn * 32 + nt * 8 + tig * 2;
                float b0 = biasS[cl], b1 = biasS[cl + 1];
                float* d0 = &g_xp[(size_t)r0 * 1536 + n0 + cl];
                float* d1 = &g_xp[(size_t)(r0 + 8) * 1536 + n0 + cl];
                *(float2*)d0 = make_float2(acc[mt][nt][0] + b0, acc[mt][nt][1] + b1);
                *(float2*)d1 = make_float2(acc[mt][nt][2] + b0, acc[mt][nt][3] + b1);
            }
        }
    }
}

// ======================= recurrence v10: HMMA + bf16 h exchange ==============
// = R12 (verified 4817us) with h double-buffered as SPLIT bf16 planes in
// global: consumer stores hi/lo directly; staging (t>0) is a pure copy loop
// (no per-step split ALU). Numerically identical to R12.
#define WSTR   1040
#define SM_WHC 0
#define SM_WHA 66560
#define SM_HH  133120
#define SM_HL  166400
#define SM_RED 199680
#define SM_REC_TOT 216064
#define LODELTA 33280

__global__ void __launch_bounds__(512, 1) recur_kernel(
    const float* __restrict__ h_in,
    const float* __restrict__ Wc, const float* __restrict__ Wa,
    float* __restrict__ out)
{
    extern __shared__ __align__(1024) char smem[];
    const uint32_t sb = smem_u32(smem);
    float4* RedF4 = (float4*)(smem + SM_RED);
    const float2* RedF2 = (const float2*)(smem + SM_RED);

    const int ct = blockIdx.x;
    const int jt = ct & 15, bt = ct >> 4;
    const int j0 = jt * 32, b0 = bt * 32;
    const int tid = threadIdx.x;
    const int w = tid >> 5, lane = tid & 31;
    const int ks = w & 3, mat = (w >> 2) & 1, mt = w >> 3;

    // ldmatrix bases (identical to R12)
    const int msel = lane >> 3;
    const uint32_t abase = sb + SM_HH +
        (mt * 16 + (msel & 1) * 8 + (lane & 7)) * WSTR + (msel >> 1) * 16;
    uint32_t b_base[4];
    #pragma unroll
    for (int nt = 0; nt < 4; nt++)
        b_base[nt] = sb + (mat ? SM_WHA : SM_WHC) +
            (nt * 8 + (lane & 7)) * WSTR + ((lane >> 3) & 1) * 16;

    // consumer mapping (identical to R12)
    const int cb = tid >> 4, jp = tid & 15;
    const int cmt = cb >> 4, cqh = (cb >> 3) & 1, cgid = cb & 7;
    const int clane = cgid * 4 + (jp & 3);
    const int cntc = jp >> 2;

    // ---- one-time: stage W hi/lo (both mats) ----
    for (int idx = tid; idx < 8192; idx += 512) {
        int m = idx >> 12;
        int j = (idx >> 7) & 31;
        int kc = idx & 127;
        const float* src = (m ? Wa : Wc) + (size_t)(j0 + j) * HID + kc * 4;
        float4 v = __ldcg((const float4*)src);
        uint2 hi, lo; split4(v, hi, lo);
        char* bp = smem + (m ? SM_WHA : SM_WHC) + j * WSTR + kc * 8;
        *(uint2*)bp = hi;
        *(uint2*)(bp + LODELTA) = lo;
    }

    unsigned* cnt = &g_cnt[bt * 32];
    unsigned* gen = &g_gen[bt * 32];
    __shared__ unsigned s_g0;
    if (tid == 0) s_g0 = *gen;
    __syncthreads();
    const unsigned g0 = s_g0;

    // xp prefetch t=0
    float2 xc, xa, xh;
    {
        const size_t crow0 = (size_t)b0 + cb;
        const float* xpb = &g_xp[crow0 * 1536 + j0 + jp * 2];
        xc = __ldcg((const float2*)(xpb));
        xa = __ldcg((const float2*)(xpb + 512));
        xh = __ldcg((const float2*)(xpb + 1024));
    }

    for (int t = 0; t < SEQ; t++) {
        // ---- stage h tile ----
        if (t == 0) {
            // fp32 h_in -> split on the fly (one-time)
            for (int i = tid; i < 32 * 128; i += 512) {
                int r = i >> 7, kc = i & 127;
                float4 v = __ldcg((const float4*)&h_in[(size_t)(b0 + r) * HID + kc * 4]);
                uint2 hi, lo; split4(v, hi, lo);
                char* bp = smem + SM_HH + r * WSTR + kc * 8;
                *(uint2*)bp = hi;
                *(uint2*)(bp + LODELTA) = lo;
            }
        } else {
            // THE DELTA: pure uint4 copy from pre-split bf16 planes
            const uint32_t* srcb = g_hb[t & 1][0];
            const uint32_t* srcl = g_hb[t & 1][1];
            for (int i = tid; i < 4096; i += 512) {
                int plane = i >> 11;
                int rem = i & 2047;
                int r = rem >> 6;          // 0..31
                int c = rem & 63;          // uint4 within 1024B row
                const uint32_t* src = plane ? srcl : srcb;
                uint4 v = __ldcg((const uint4*)src + (size_t)(b0 + r) * 64 + c);
                *(uint4*)(smem + (plane ? SM_HL : SM_HH) + r * WSTR + c * 16) = v;
            }
        }
        __syncthreads();

        // ---- HMMA matvec (identical to R12) ----
        float acc[4][4];
        #pragma unroll
        for (int nt = 0; nt < 4; nt++)
            #pragma unroll
            for (int q = 0; q < 4; q++) acc[nt][q] = 0.0f;

        #pragma unroll
        for (int kstep = 0; kstep < 8; kstep++) {
            const uint32_t kb = ks * 256 + kstep * 32;
            uint32_t ahf[4], alf[4];
            ldsm4(ahf[0], ahf[1], ahf[2], ahf[3], abase + kb);
            ldsm4(alf[0], alf[1], alf[2], alf[3], abase + LODELTA + kb);
            uint32_t bhf[4][2], blf[4][2];
            #pragma unroll
            for (int nt = 0; nt < 4; nt++) {
                ldsm2(bhf[nt][0], bhf[nt][1], b_base[nt] + kb);
                ldsm2(blf[nt][0], blf[nt][1], b_base[nt] + LODELTA + kb);
            }
            #pragma unroll
            for (int nt = 0; nt < 4; nt++) {
                mma16816(acc[nt], ahf, bhf[nt]);
                mma16816(acc[nt], ahf, blf[nt]);
                mma16816(acc[nt], alf, bhf[nt]);
            }
        }

        // ---- reduction (identical to R12) ----
        const int rgbase = (mat * 2 + mt) * 2;
        if (ks < 2) {
            #pragma unroll
            for (int nt = 0; nt < 4; nt++)
                RedF4[(rgbase + ks) * 128 + lane * 4 + nt] =
                    make_float4(acc[nt][0], acc[nt][1], acc[nt][2], acc[nt][3]);
        }
        __syncthreads();
        if (ks >= 2) {
            #pragma unroll
            for (int nt = 0; nt < 4; nt++) {
                const int idx = (rgbase + ks - 2) * 128 + lane * 4 + nt;
                float4 v = RedF4[idx];
                v.x += acc[nt][0]; v.y += acc[nt][1];
                v.z += acc[nt][2]; v.w += acc[nt][3];
                RedF4[idx] = v;
            }
        }
        __syncthreads();

        // ---- consumer: gather hc/ha, reconstruct hp, gated epilogue ----
        {
            const int f4c = cmt * 2 * 128 + clane * 4 + cntc;
            const int f4a = (cmt * 2 + 4) * 128 + clane * 4 + cntc;
            float2 c0 = RedF2[(f4c) * 2 + cqh];
            float2 c1 = RedF2[(f4c + 128) * 2 + cqh];
            float2 a0 = RedF2[(f4a) * 2 + cqh];
            float2 a1 = RedF2[(f4a + 128) * 2 + cqh];
            float2 hc = make_float2(c0.x + c1.x, c0.y + c1.y);
            float2 ha = make_float2(a0.x + a1.x, a0.y + a1.y);

            const uint32_t hb = *(const uint32_t*)(smem + SM_HH + cb * WSTR +
                                                   (j0 + jp * 2) * 2);
            const uint32_t lb = *(const uint32_t*)(smem + SM_HL + cb * WSTR +
                                                   (j0 + jp * 2) * 2);
            float hp0 = __bfloat162float(__ushort_as_bfloat16((unsigned short)(hb & 0xFFFF)))
                      + __bfloat162float(__ushort_as_bfloat16((unsigned short)(lb & 0xFFFF)));
            float hp1 = __bfloat162float(__ushort_as_bfloat16((unsigned short)(hb >> 16)))
                      + __bfloat162float(__ushort_as_bfloat16((unsigned short)(lb >> 16)));

            const size_t crow = (size_t)t * BATCH + b0 + cb;
            float r0, r1;
            {
                float cg = sig_f(xc.x + hc.x);
                float ag = 1.0f + tanh_f(xa.x + ha.x);
                r0 = cg * hp0 + (1.0f - cg) * tanh_f(xh.x + ag * hp0);
            }
            {
                float cg = sig_f(xc.y + hc.y);
                float ag = 1.0f + tanh_f(xa.y + ha.y);
                r1 = cg * hp1 + (1.0f - cg) * tanh_f(xh.y + ag * hp1);
            }
            // y (fp32) out
            *(float2*)&out[crow * HID + j0 + jp * 2] = make_float2(r0, r1);
            // h(t+1): store split bf16 hi/lo directly (bit-identical to
            // splitting a stored fp32 on the next step)
            __nv_bfloat16 h0b = __float2bfloat16_rn(r0);
            __nv_bfloat16 h1b = __float2bfloat16_rn(r1);
            __nv_bfloat16 l0b = __float2bfloat16_rn(r0 - __bfloat162float(h0b));
            __nv_bfloat16 l1b = __float2bfloat16_rn(r1 - __bfloat162float(h1b));
            const int hidx = (b0 + cb) * 256 + (j0 >> 1) + jp;
            g_hb[(t + 1) & 1][0][hidx] = pck(h0b, h1b);
            g_hb[(t + 1) & 1][1][hidx] = pck(l0b, l1b);
            if (t == SEQ - 1)
                *(float2*)&out[(size_t)SEQ * BATCH * HID +
                               (size_t)(b0 + cb) * HID + j0 + jp * 2] =
                    make_float2(r0, r1);
        }

        // ---- prefetch next xp, then counting barrier (identical to R12) ----
        if (t < SEQ - 1) {
            const size_t nrow = (size_t)(t + 1) * BATCH + b0 + cb;
            const float* nxpb = &g_xp[nrow * 1536 + j0 + jp * 2];
            xc = __ldcg((const float2*)(nxpb));
            xa = __ldcg((const float2*)(nxpb + 512));
            xh = __ldcg((const float2*)(nxpb + 1024));

            __syncthreads();
            if (tid == 0) {
                __threadfence();
                const unsigned target = g0 + (unsigned)t + 1u;
                if (atomicAdd(cnt, 1u) == 15u) {
                    atomicExch(cnt, 0u);
                    __threadfence();
                    st_rel(gen, target);
                } else {
                    while (ld_acq(gen) != target) { }
                }
            }
            __syncthreads();
        }
    }
}

// ============================================================================
extern "C" void kernel_launch(void* const* d_in, const int* in_sizes, int n_in,
                              void* d_out, int out_size)
{
    const float* X  = (const float*)d_in[0];
    const float* h0 = (const float*)d_in[1];
    const float* Uc = (const float*)d_in[2];
    const float* Wc = (const float*)d_in[3];
    const float* bc = (const float*)d_in[4];
    const float* Ua = (const float*)d_in[5];
    const float* Wa = (const float*)d_in[6];
    const float* ba = (const float*)d_in[7];
    const float* Uh = (const float*)d_in[8];
    const float* bh = (const float*)d_in[9];
    float* out = (float*)d_out;

    cudaFuncSetAttribute(proj_mma_kernel, cudaFuncAttributeMaxDynamicSharedMemorySize,
                         SM_PROJ_TOT);
    cudaFuncSetAttribute(recur_kernel, cudaFuncAttributeMaxDynamicSharedMemorySize,
                         SM_REC_TOT);

    xsplit_kernel<<<4096, 256>>>(X);
    usplit_kernel<<<384, 256>>>(Uc, Ua, Uh);
    dim3 pg(24, 128);
    proj_mma_kernel<<<pg, 256, SM_PROJ_TOT>>>(bc, ba, bh);
    recur_kernel<<<128, 512, SM_REC_TOT>>>(h0, Wc, Wa, out);
}

// round 14
// speedup vs baseline: 2.8710x; 1.0510x over previous
#include <cuda_runtime.h>
#include <cuda_bf16.h>
#include <cstddef>
#include <cstdint>
#include <math.h>

#define SEQ   512
#define BATCH 256
#define INP   256
#define HID   512

typedef unsigned long long u64;

// ---------- sync helpers ----------
__device__ __forceinline__ unsigned ld_acq(const unsigned* p) {
    unsigned v;
    asm volatile("ld.acquire.gpu.global.b32 %0,[%1];" : "=r"(v) : "l"(p) : "memory");
    return v;
}
__device__ __forceinline__ void st_rel(unsigned* p, unsigned v) {
    asm volatile("st.release.gpu.global.b32 [%0],%1;" :: "l"(p), "r"(v) : "memory");
}
__device__ __forceinline__ unsigned atom_add_acqrel(unsigned* p, unsigned v) {
    unsigned old;
    asm volatile("atom.add.acq_rel.gpu.global.u32 %0,[%1],%2;"
                 : "=r"(old) : "l"(p), "r"(v) : "memory");
    return old;
}

// ---------- fast activations ----------
__device__ __forceinline__ float sig_f(float z) {
    return __fdividef(1.0f, 1.0f + __expf(-z));
}
__device__ __forceinline__ float tanh_f(float z) {
    return 1.0f - __fdividef(2.0f, __expf(2.0f * z) + 1.0f);
}

// ---------- scratch ----------
__device__ float g_xp[(size_t)SEQ * BATCH * 3 * HID];
__device__ uint32_t g_hb[2][2][BATCH * HID / 2];   // [buf][plane hi/lo][b*256 + j/2]
__device__ unsigned g_cnt[8 * 32];
__device__ unsigned g_gen[8 * 32];
__device__ __nv_bfloat16 g_xh[(size_t)SEQ * BATCH * INP];
__device__ __nv_bfloat16 g_xl[(size_t)SEQ * BATCH * INP];
__device__ __nv_bfloat16 g_uh[3 * HID * INP];
__device__ __nv_bfloat16 g_ul[3 * HID * INP];

// ---------- split helpers ----------
__device__ __forceinline__ uint32_t pck(__nv_bfloat16 a, __nv_bfloat16 b) {
    return (uint32_t)__bfloat16_as_ushort(a) | ((uint32_t)__bfloat16_as_ushort(b) << 16);
}
__device__ __forceinline__ void split4(float4 v, uint2& hi, uint2& lo) {
    __nv_bfloat16 h0 = __float2bfloat16_rn(v.x), h1 = __float2bfloat16_rn(v.y);
    __nv_bfloat16 h2 = __float2bfloat16_rn(v.z), h3 = __float2bfloat16_rn(v.w);
    __nv_bfloat16 l0 = __float2bfloat16_rn(v.x - __bfloat162float(h0));
    __nv_bfloat16 l1 = __float2bfloat16_rn(v.y - __bfloat162float(h1));
    __nv_bfloat16 l2 = __float2bfloat16_rn(v.z - __bfloat162float(h2));
    __nv_bfloat16 l3 = __float2bfloat16_rn(v.w - __bfloat162float(h3));
    hi = make_uint2(pck(h0, h1), pck(h2, h3));
    lo = make_uint2(pck(l0, l1), pck(l2, l3));
}

__global__ void __launch_bounds__(256) xsplit_kernel(const float* __restrict__ X) {
    const size_t total = (size_t)SEQ * BATCH * INP / 4;
    for (size_t f4 = (size_t)blockIdx.x * 256 + threadIdx.x; f4 < total;
         f4 += (size_t)gridDim.x * 256) {
        float4 v = __ldcg((const float4*)X + f4);
        uint2 hi, lo; split4(v, hi, lo);
        ((uint2*)g_xh)[f4] = hi;
        ((uint2*)g_xl)[f4] = lo;
    }
}

__global__ void __launch_bounds__(256) usplit_kernel(
    const float* __restrict__ Uc, const float* __restrict__ Ua,
    const float* __restrict__ Uh)
{
    const int mat = blockIdx.x >> 7;
    const int f4 = (blockIdx.x & 127) * 256 + threadIdx.x;
    const float* src = (mat == 0) ? Uc : (mat == 1 ? Ua : Uh);
    float4 v = __ldcg((const float4*)src + f4);
    uint2 hi, lo; split4(v, hi, lo);
    ((uint2*)g_uh)[mat * 32768 + f4] = hi;
    ((uint2*)g_ul)[mat * 32768 + f4] = lo;
}

// ---------- mma / ldmatrix ----------
__device__ __forceinline__ uint32_t smem_u32(const void* p) {
    uint32_t a;
    asm("{ .reg .u64 t; cvta.to.shared.u64 t,%1; cvt.u32.u64 %0,t; }" : "=r"(a) : "l"(p));
    return a;
}
__device__ __forceinline__ void ldsm4(uint32_t& r0, uint32_t& r1, uint32_t& r2,
                                      uint32_t& r3, uint32_t a) {
    asm volatile("ldmatrix.sync.aligned.m8n8.x4.shared.b16 {%0,%1,%2,%3},[%4];"
                 : "=r"(r0), "=r"(r1), "=r"(r2), "=r"(r3) : "r"(a));
}
__device__ __forceinline__ void ldsm2(uint32_t& r0, uint32_t& r1, uint32_t a) {
    asm volatile("ldmatrix.sync.aligned.m8n8.x2.shared.b16 {%0,%1},[%2];"
                 : "=r"(r0), "=r"(r1) : "r"(a));
}
__device__ __forceinline__ void mma16816(float* d, const uint32_t* a, const uint32_t* b) {
    asm volatile(
        "mma.sync.aligned.m16n8k16.row.col.f32.bf16.bf16.f32 "
        "{%0,%1,%2,%3},{%4,%5,%6,%7},{%8,%9},{%0,%1,%2,%3};"
        : "+f"(d[0]), "+f"(d[1]), "+f"(d[2]), "+f"(d[3])
        : "r"(a[0]), "r"(a[1]), "r"(a[2]), "r"(a[3]), "r"(b[0]), "r"(b[1]));
}

// ======================= projection (unchanged from R11) =====================
#define PSTR 528
#define SM_PBIAS 0
#define SM_BH 1024
#define SM_BL (SM_BH + 64 * PSTR)
#define SM_AH (SM_BL + 64 * PSTR)
#define SM_AL (SM_AH + 128 * PSTR)
#define SM_PROJ_TOT (SM_AL + 128 * PSTR)

__global__ void __launch_bounds__(256, 1) proj_mma_kernel(
    const float* __restrict__ bc, const float* __restrict__ ba,
    const float* __restrict__ bh)
{
    extern __shared__ __align__(1024) char smem[];
    const uint32_t sb = smem_u32(smem);
    const int tid = threadIdx.x;
    const int wid = tid >> 5;
    const int lane = tid & 31;

    const int n0 = blockIdx.x * 64;
    const int region = n0 >> 9;
    const int nl0 = n0 & 511;
    const float* __restrict__ bias = (region == 0) ? bc : (region == 1 ? ba : bh);
    float* biasS = (float*)(smem + SM_PBIAS);
    if (tid < 64) biasS[tid] = bias[nl0 + tid];

    const __nv_bfloat16* ubase_h = g_uh + (size_t)region * HID * INP;
    const __nv_bfloat16* ubase_l = g_ul + (size_t)region * HID * INP;
    for (int idx = tid; idx < 4096; idx += 256) {
        int sel = idx >> 11;
        int r = (idx >> 5) & 63, c = idx & 31;
        const __nv_bfloat16* src = (sel ? ubase_l : ubase_h) + (size_t)(nl0 + r) * INP;
        uint4 v = ((const uint4*)src)[c];
        *(uint4*)(smem + (sel ? SM_BL : SM_BH) + r * PSTR + c * 16) = v;
    }

    const int wm = wid & 3, wn = wid >> 2;
    const int msel = lane >> 3;
    const int arow = (msel & 1) * 8 + (lane & 7);
    const int acol16 = (msel >> 1);
    uint32_t a_base[2];
    #pragma unroll
    for (int mt = 0; mt < 2; mt++)
        a_base[mt] = sb + SM_AH + (wm * 32 + mt * 16 + arow) * PSTR + acol16 * 16;
    uint32_t b_base[4];
    #pragma unroll
    for (int nt = 0; nt < 4; nt++)
        b_base[nt] = sb + SM_BH + (wn * 32 + nt * 8 + (lane & 7)) * PSTR
                   + ((lane >> 3) & 1) * 16;
    const uint32_t ADL = SM_AL - SM_AH;
    const uint32_t BDL = SM_BL - SM_BH;

    for (int i = 0; i < 8; i++) {
        const int m0 = (blockIdx.y * 8 + i) * 128;
        __syncthreads();

        for (int idx = tid; idx < 8192; idx += 256) {
            int sel = idx >> 12;
            int r = (idx >> 5) & 127, c = idx & 31;
            const __nv_bfloat16* src = (sel ? g_xl : g_xh) + (size_t)(m0 + r) * INP;
            uint4 v = __ldcg((const uint4*)src + c);
            *(uint4*)(smem + (sel ? SM_AL : SM_AH) + r * PSTR + c * 16) = v;
        }
        __syncthreads();

        float acc[2][4][4];
        #pragma unroll
        for (int mt = 0; mt < 2; mt++)
            #pragma unroll
            for (int nt = 0; nt < 4; nt++)
                #pragma unroll
                for (int q = 0; q < 4; q++) acc[mt][nt][q] = 0.0f;

        #pragma unroll 4
        for (int ks = 0; ks < 16; ks++) {
            const uint32_t kb = ks * 32;
            uint32_t bhf[4][2], blf[4][2];
            #pragma unroll
            for (int nt = 0; nt < 4; nt++) {
                ldsm2(bhf[nt][0], bhf[nt][1], b_base[nt] + kb);
                ldsm2(blf[nt][0], blf[nt][1], b_base[nt] + BDL + kb);
            }
            uint32_t ahf[2][4], alf[2][4];
            #pragma unroll
            for (int mt = 0; mt < 2; mt++) {
                ldsm4(ahf[mt][0], ahf[mt][1], ahf[mt][2], ahf[mt][3], a_base[mt] + kb);
                ldsm4(alf[mt][0], alf[mt][1], alf[mt][2], alf[mt][3],
                      a_base[mt] + ADL + kb);
            }
            #pragma unroll
            for (int mt = 0; mt < 2; mt++)
                #pragma unroll
                for (int nt = 0; nt < 4; nt++)
                    mma16816(acc[mt][nt], ahf[mt], bhf[nt]);
            #pragma unroll
            for (int mt = 0; mt < 2; mt++)
                #pragma unroll
                for (int nt = 0; nt < 4; nt++)
                    mma16816(acc[mt][nt], ahf[mt], blf[nt]);
            #pragma unroll
            for (int mt = 0; mt < 2; mt++)
                #pragma unroll
                for (int nt = 0; nt < 4; nt++)
                    mma16816(acc[mt][nt], alf[mt], bhf[nt]);
        }

        const int gid = lane >> 2, tig = lane & 3;
        #pragma unroll
        for (int mt = 0; mt < 2; mt++) {
            const int r0 = m0 + wm * 32 + mt * 16 + gid;
            #pragma unroll
            for (int nt = 0; nt < 4; nt++) {
                const int cl = wn * 32 + nt * 8 + tig * 2;
                float b0 = biasS[cl], b1 = biasS[cl + 1];
                float* d0 = &g_xp[(size_t)r0 * 1536 + n0 + cl];
                float* d1 = &g_xp[(size_t)(r0 + 8) * 1536 + n0 + cl];
                *(float2*)d0 = make_float2(acc[mt][nt][0] + b0, acc[mt][nt][1] + b1);
                *(float2*)d1 = make_float2(acc[mt][nt][2] + b0, acc[mt][nt][3] + b1);
            }
        }
    }
}

// ======================= recurrence v11: shortened serial chain ==============
// = R13 (verified 4626us) with: (1) single-round 16-region reduction (one
// sync instead of two, no RMW round; addition order preserved — numerics
// identical), (2) acq_rel counting barrier (no threadfence), (3) cp.async
// h staging. Matvec / mappings / stores unchanged.
#define WSTR   1040
#define SM_WHC 0
#define SM_WHA 66560
#define SM_HH  133120
#define SM_HL  166400
#define SM_RED 199680
#define SM_REC_TOT 232448                  // = sharedMemPerBlockOptin (227 KB)
#define LODELTA 33280

__global__ void __launch_bounds__(512, 1) recur_kernel(
    const float* __restrict__ h_in,
    const float* __restrict__ Wc, const float* __restrict__ Wa,
    float* __restrict__ out)
{
    extern __shared__ __align__(1024) char smem[];
    const uint32_t sb = smem_u32(smem);
    float4* RedF4 = (float4*)(smem + SM_RED);
    const float2* RedF2 = (const float2*)(smem + SM_RED);

    const int ct = blockIdx.x;
    const int jt = ct & 15, bt = ct >> 4;
    const int j0 = jt * 32, b0 = bt * 32;
    const int tid = threadIdx.x;
    const int w = tid >> 5, lane = tid & 31;
    const int ks = w & 3, mat = (w >> 2) & 1, mt = w >> 3;

    // ldmatrix bases (identical to R13)
    const int msel = lane >> 3;
    const uint32_t abase = sb + SM_HH +
        (mt * 16 + (msel & 1) * 8 + (lane & 7)) * WSTR + (msel >> 1) * 16;
    uint32_t b_base[4];
    #pragma unroll
    for (int nt = 0; nt < 4; nt++)
        b_base[nt] = sb + (mat ? SM_WHA : SM_WHC) +
            (nt * 8 + (lane & 7)) * WSTR + ((lane >> 3) & 1) * 16;

    // consumer mapping (identical to R13)
    const int cb = tid >> 4, jp = tid & 15;
    const int cmt = cb >> 4, cqh = (cb >> 3) & 1, cgid = cb & 7;
    const int clane = cgid * 4 + (jp & 3);
    const int cntc = jp >> 2;
    const int cfbase = cmt * 4 * 128 + clane * 4 + cntc;   // f4 idx, mat0 ks0

    // producer region (16 regions x 128 float4)
    const int preg = mat * 8 + mt * 4 + ks;

    // ---- one-time: stage W hi/lo (both mats) ----
    for (int idx = tid; idx < 8192; idx += 512) {
        int m = idx >> 12;
        int j = (idx >> 7) & 31;
        int kc = idx & 127;
        const float* src = (m ? Wa : Wc) + (size_t)(j0 + j) * HID + kc * 4;
        float4 v = __ldcg((const float4*)src);
        uint2 hi, lo; split4(v, hi, lo);
        char* bp = smem + (m ? SM_WHA : SM_WHC) + j * WSTR + kc * 8;
        *(uint2*)bp = hi;
        *(uint2*)(bp + LODELTA) = lo;
    }

    unsigned* cnt = &g_cnt[bt * 32];
    unsigned* gen = &g_gen[bt * 32];
    unsigned g0 = 0;
    if (tid == 0) g0 = *gen;   // safe: gen can't advance before this CTA arrives

    // xp prefetch t=0
    float2 xc, xa, xh;
    {
        const size_t crow0 = (size_t)b0 + cb;
        const float* xpb = &g_xp[crow0 * 1536 + j0 + jp * 2];
        xc = __ldcg((const float2*)(xpb));
        xa = __ldcg((const float2*)(xpb + 512));
        xh = __ldcg((const float2*)(xpb + 1024));
    }

    for (int t = 0; t < SEQ; t++) {
        // ---- stage h tile ----
        if (t == 0) {
            for (int i = tid; i < 32 * 128; i += 512) {
                int r = i >> 7, kc = i & 127;
                float4 v = __ldcg((const float4*)&h_in[(size_t)(b0 + r) * HID + kc * 4]);
                uint2 hi, lo; split4(v, hi, lo);
                char* bp = smem + SM_HH + r * WSTR + kc * 8;
                *(uint2*)bp = hi;
                *(uint2*)(bp + LODELTA) = lo;
            }
        } else {
            // cp.async copy from pre-split bf16 planes
            const uint32_t* srcb = g_hb[t & 1][0];
            const uint32_t* srcl = g_hb[t & 1][1];
            for (int i = tid; i < 4096; i += 512) {
                int plane = i >> 11;
                int rem = i & 2047;
                int r = rem >> 6;
                int c = rem & 63;
                const uint32_t* src = plane ? srcl : srcb;
                const void* gaddr = (const char*)src + ((size_t)(b0 + r) * 64 + c) * 16;
                uint32_t daddr = sb + (plane ? SM_HL : SM_HH) + r * WSTR + c * 16;
                asm volatile("cp.async.ca.shared.global [%0],[%1],16;"
                             :: "r"(daddr), "l"(gaddr) : "memory");
            }
            asm volatile("cp.async.commit_group;" ::: "memory");
            asm volatile("cp.async.wait_group 0;" ::: "memory");
        }
        __syncthreads();

        // ---- HMMA matvec (identical to R13) ----
        float acc[4][4];
        #pragma unroll
        for (int nt = 0; nt < 4; nt++)
            #pragma unroll
            for (int q = 0; q < 4; q++) acc[nt][q] = 0.0f;

        #pragma unroll
        for (int kstep = 0; kstep < 8; kstep++) {
            const uint32_t kb = ks * 256 + kstep * 32;
            uint32_t ahf[4], alf[4];
            ldsm4(ahf[0], ahf[1], ahf[2], ahf[3], abase + kb);
            ldsm4(alf[0], alf[1], alf[2], alf[3], abase + LODELTA + kb);
            uint32_t bhf[4][2], blf[4][2];
            #pragma unroll
            for (int nt = 0; nt < 4; nt++) {
                ldsm2(bhf[nt][0], bhf[nt][1], b_base[nt] + kb);
                ldsm2(blf[nt][0], blf[nt][1], b_base[nt] + LODELTA + kb);
            }
            #pragma unroll
            for (int nt = 0; nt < 4; nt++) {
                mma16816(acc[nt], ahf, bhf[nt]);
                mma16816(acc[nt], ahf, blf[nt]);
                mma16816(acc[nt], alf, bhf[nt]);
            }
        }

        // ---- single-round reduction: every warp stores its own region ----
        #pragma unroll
        for (int nt = 0; nt < 4; nt++)
            RedF4[preg * 128 + lane * 4 + nt] =
                make_float4(acc[nt][0], acc[nt][1], acc[nt][2], acc[nt][3]);
        __syncthreads();

        // ---- consumer: sum 4 partials (order matches R13), epilogue ----
        {
            float2 rc[4], ra[4];
            #pragma unroll
            for (int r = 0; r < 4; r++) {
                rc[r] = RedF2[(cfbase + r * 128) * 2 + cqh];
                ra[r] = RedF2[(cfbase + 1024 + r * 128) * 2 + cqh];
            }
            float2 hc = make_float2((rc[0].x + rc[2].x) + (rc[1].x + rc[3].x),
                                    (rc[0].y + rc[2].y) + (rc[1].y + rc[3].y));
            float2 ha = make_float2((ra[0].x + ra[2].x) + (ra[1].x + ra[3].x),
                                    (ra[0].y + ra[2].y) + (ra[1].y + ra[3].y));

            const uint32_t hb = *(const uint32_t*)(smem + SM_HH + cb * WSTR +
                                                   (j0 + jp * 2) * 2);
            const uint32_t lb = *(const uint32_t*)(smem + SM_HL + cb * WSTR +
                                                   (j0 + jp * 2) * 2);
            float hp0 = __bfloat162float(__ushort_as_bfloat16((unsigned short)(hb & 0xFFFF)))
                      + __bfloat162float(__ushort_as_bfloat16((unsigned short)(lb & 0xFFFF)));
            float hp1 = __bfloat162float(__ushort_as_bfloat16((unsigned short)(hb >> 16)))
                      + __bfloat162float(__ushort_as_bfloat16((unsigned short)(lb >> 16)));

            const size_t crow = (size_t)t * BATCH + b0 + cb;
            float r0, r1;
            {
                float cg = sig_f(xc.x + hc.x);
                float ag = 1.0f + tanh_f(xa.x + ha.x);
                r0 = cg * hp0 + (1.0f - cg) * tanh_f(xh.x + ag * hp0);
            }
            {
                float cg = sig_f(xc.y + hc.y);
                float ag = 1.0f + tanh_f(xa.y + ha.y);
                r1 = cg * hp1 + (1.0f - cg) * tanh_f(xh.y + ag * hp1);
            }
            *(float2*)&out[crow * HID + j0 + jp * 2] = make_float2(r0, r1);
            __nv_bfloat16 h0b = __float2bfloat16_rn(r0);
            __nv_bfloat16 h1b = __float2bfloat16_rn(r1);
            __nv_bfloat16 l0b = __float2bfloat16_rn(r0 - __bfloat162float(h0b));
            __nv_bfloat16 l1b = __float2bfloat16_rn(r1 - __bfloat162float(h1b));
            const int hidx = (b0 + cb) * 256 + (j0 >> 1) + jp;
            g_hb[(t + 1) & 1][0][hidx] = pck(h0b, h1b);
            g_hb[(t + 1) & 1][1][hidx] = pck(l0b, l1b);
            if (t == SEQ - 1)
                *(float2*)&out[(size_t)SEQ * BATCH * HID +
                               (size_t)(b0 + cb) * HID + j0 + jp * 2] =
                    make_float2(r0, r1);
        }

        // ---- prefetch next xp, then fence-fused counting barrier ----
        if (t < SEQ - 1) {
            const size_t nrow = (size_t)(t + 1) * BATCH + b0 + cb;
            const float* nxpb = &g_xp[nrow * 1536 + j0 + jp * 2];
            xc = __ldcg((const float2*)(nxpb));
            xa = __ldcg((const float2*)(nxpb + 512));
            xh = __ldcg((const float2*)(nxpb + 1024));

            __syncthreads();
            if (tid == 0) {
                const unsigned target = g0 + (unsigned)t + 1u;
                if (atom_add_acqrel(cnt, 1u) == 15u) {
                    atomicExch(cnt, 0u);
                    st_rel(gen, target);           // release covers the reset
                } else {
                    while (ld_acq(gen) != target) { }
                }
            }
            __syncthreads();
        }
    }
}

// ============================================================================
extern "C" void kernel_launch(void* const* d_in, const int* in_sizes, int n_in,
                              void* d_out, int out_size)
{
    const float* X  = (const float*)d_in[0];
    const float* h0 = (const float*)d_in[1];
    const float* Uc = (const float*)d_in[2];
    const float* Wc = (const float*)d_in[3];
    const float* bc = (const float*)d_in[4];
    const float* Ua = (const float*)d_in[5];
    const float* Wa = (const float*)d_in[6];
    const float* ba = (const float*)d_in[7];
    const float* Uh = (const float*)d_in[8];
    const float* bh = (const float*)d_in[9];
    float* out = (float*)d_out;

    cudaFuncSetAttribute(proj_mma_kernel, cudaFuncAttributeMaxDynamicSharedMemorySize,
                         SM_PROJ_TOT);
    cudaFuncSetAttribute(recur_kernel, cudaFuncAttributeMaxDynamicSharedMemorySize,
                         SM_REC_TOT);

    xsplit_kernel<<<4096, 256>>>(X);
    usplit_kernel<<<384, 256>>>(Uc, Ua, Uh);
    dim3 pg(24, 128);
    proj_mma_kernel<<<pg, 256, SM_PROJ_TOT>>>(bc, ba, bh);
    recur_kernel<<<128, 512, SM_REC_TOT>>>(h0, Wc, Wa, out);
}